// round 2
// baseline (speedup 1.0000x reference)
#include <cuda_runtime.h>
#include <cuda_bf16.h>
#include <stdint.h>
#include <stddef.h>

// Problem dims (fixed by the reference)
#define T_DIM 2048
#define B_DIM 16
#define D_DIM 1024
#define M_DIM (T_DIM * B_DIM)   // 32768

// Scratch (no cudaMalloc allowed): interleaved {alpha, c} per element,
// c = (1-alpha)*tanh(x@Wx^T + b_v)
__device__ float2 g_ac[(size_t)M_DIM * D_DIM];

// ---------------- GEMM: C = x @ W^T for BOTH weight matrices, split-bf16 (3 products) ----
#define BM 128
#define BN 64
#define BK 32
#define SMSTRIDE 40   // bf16 elems per smem row (32 data + 8 pad) -> 80B stride, conflict-free frags

__device__ __forceinline__ void mma_bf16(float* c, const uint32_t* a, const uint32_t* b) {
    asm volatile(
        "mma.sync.aligned.m16n8k16.row.col.f32.bf16.bf16.f32 "
        "{%0,%1,%2,%3}, {%4,%5,%6,%7}, {%8,%9}, {%0,%1,%2,%3};\n"
        : "+f"(c[0]), "+f"(c[1]), "+f"(c[2]), "+f"(c[3])
        : "r"(a[0]), "r"(a[1]), "r"(a[2]), "r"(a[3]), "r"(b[0]), "r"(b[1]));
}

__device__ __forceinline__ void split_store(__nv_bfloat16* sh, __nv_bfloat16* sl,
                                            int r, int c, float4 v) {
    float f[4] = {v.x, v.y, v.z, v.w};
#pragma unroll
    for (int e = 0; e < 4; e++) {
        __nv_bfloat16 hi = __float2bfloat16(f[e]);
        float rem = f[e] - __bfloat162float(hi);
        __nv_bfloat16 lo = __float2bfloat16(rem);
        sh[r * SMSTRIDE + c + e] = hi;
        sl[r * SMSTRIDE + c + e] = lo;
    }
}

__global__ __launch_bounds__(256, 1)
void gemm2_kernel(const float* __restrict__ x,
                  const float* __restrict__ Wa,
                  const float* __restrict__ Wx,
                  const float* __restrict__ b_alpha,
                  const float* __restrict__ b_v)
{
    __shared__ __nv_bfloat16 sXh[BM * SMSTRIDE];
    __shared__ __nv_bfloat16 sXl[BM * SMSTRIDE];
    __shared__ __nv_bfloat16 sAh[BN * SMSTRIDE];
    __shared__ __nv_bfloat16 sAl[BN * SMSTRIDE];
    __shared__ __nv_bfloat16 sBh[BN * SMSTRIDE];
    __shared__ __nv_bfloat16 sBl[BN * SMSTRIDE];

    const int tid = threadIdx.x;
    const int bx = blockIdx.x;           // N block (0..15)  — fastest => x strip L2 reuse
    const int by = blockIdx.y;           // M block (0..255)
    const int m_base = by * BM;
    const int n_base = bx * BN;

    const int warp = tid >> 5;
    const int lane = tid & 31;
    const int grp = lane >> 2;           // 0..7
    const int tig = lane & 3;            // 0..3
    const int wm = (warp >> 2) * 64;     // warp M offset: 0 or 64
    const int wn = (warp & 3) * 16;      // warp N offset: 0,16,32,48

    float accA[4][2][4];
    float accX[4][2][4];
#pragma unroll
    for (int i = 0; i < 4; i++)
#pragma unroll
        for (int j = 0; j < 2; j++)
#pragma unroll
            for (int r = 0; r < 4; r++) { accA[i][j][r] = 0.f; accX[i][j][r] = 0.f; }

    // global staging registers
    float4 rx[4], rwa[2], rwx[2];
    const int srow = tid >> 3;           // 0..31
    const int sc4  = tid & 7;            // 0..7  (float4 column)

    // initial load (k = 0)
#pragma unroll
    for (int p = 0; p < 4; p++)
        rx[p] = *(const float4*)&x[(size_t)(m_base + srow + p * 32) * D_DIM + sc4 * 4];
#pragma unroll
    for (int p = 0; p < 2; p++) {
        rwa[p] = *(const float4*)&Wa[(size_t)(n_base + srow + p * 32) * D_DIM + sc4 * 4];
        rwx[p] = *(const float4*)&Wx[(size_t)(n_base + srow + p * 32) * D_DIM + sc4 * 4];
    }

    for (int kk = 0; kk < D_DIM; kk += BK) {
        __syncthreads();   // previous iter's mma done before smem overwrite
        // stage (convert fp32 -> bf16 hi/lo) into smem
#pragma unroll
        for (int p = 0; p < 4; p++)
            split_store(sXh, sXl, srow + p * 32, sc4 * 4, rx[p]);
#pragma unroll
        for (int p = 0; p < 2; p++) {
            split_store(sAh, sAl, srow + p * 32, sc4 * 4, rwa[p]);
            split_store(sBh, sBl, srow + p * 32, sc4 * 4, rwx[p]);
        }
        __syncthreads();

        // prefetch next k-tile while mma runs
        if (kk + BK < D_DIM) {
            const int kn = kk + BK;
#pragma unroll
            for (int p = 0; p < 4; p++)
                rx[p] = *(const float4*)&x[(size_t)(m_base + srow + p * 32) * D_DIM + kn + sc4 * 4];
#pragma unroll
            for (int p = 0; p < 2; p++) {
                rwa[p] = *(const float4*)&Wa[(size_t)(n_base + srow + p * 32) * D_DIM + kn + sc4 * 4];
                rwx[p] = *(const float4*)&Wx[(size_t)(n_base + srow + p * 32) * D_DIM + kn + sc4 * 4];
            }
        }

#pragma unroll
        for (int ks = 0; ks < BK; ks += 16) {
            // A fragments (hi/lo), 4 m-tiles
            uint32_t ah[4][4], al[4][4];
            const int c0 = ks + tig * 2;
#pragma unroll
            for (int i = 0; i < 4; i++) {
                const int r0 = wm + i * 16 + grp;
                ah[i][0] = *(const uint32_t*)&sXh[r0 * SMSTRIDE + c0];
                ah[i][1] = *(const uint32_t*)&sXh[(r0 + 8) * SMSTRIDE + c0];
                ah[i][2] = *(const uint32_t*)&sXh[r0 * SMSTRIDE + c0 + 8];
                ah[i][3] = *(const uint32_t*)&sXh[(r0 + 8) * SMSTRIDE + c0 + 8];
                al[i][0] = *(const uint32_t*)&sXl[r0 * SMSTRIDE + c0];
                al[i][1] = *(const uint32_t*)&sXl[(r0 + 8) * SMSTRIDE + c0];
                al[i][2] = *(const uint32_t*)&sXl[r0 * SMSTRIDE + c0 + 8];
                al[i][3] = *(const uint32_t*)&sXl[(r0 + 8) * SMSTRIDE + c0 + 8];
            }
            // B fragments, 2 n-tiles, hi/lo, both matrices
            uint32_t bAh[2][2], bAl[2][2], bXh[2][2], bXl[2][2];
#pragma unroll
            for (int j = 0; j < 2; j++) {
                const int n0 = wn + j * 8 + grp;
                bAh[j][0] = *(const uint32_t*)&sAh[n0 * SMSTRIDE + c0];
                bAh[j][1] = *(const uint32_t*)&sAh[n0 * SMSTRIDE + c0 + 8];
                bAl[j][0] = *(const uint32_t*)&sAl[n0 * SMSTRIDE + c0];
                bAl[j][1] = *(const uint32_t*)&sAl[n0 * SMSTRIDE + c0 + 8];
                bXh[j][0] = *(const uint32_t*)&sBh[n0 * SMSTRIDE + c0];
                bXh[j][1] = *(const uint32_t*)&sBh[n0 * SMSTRIDE + c0 + 8];
                bXl[j][0] = *(const uint32_t*)&sBl[n0 * SMSTRIDE + c0];
                bXl[j][1] = *(const uint32_t*)&sBl[n0 * SMSTRIDE + c0 + 8];
            }
#pragma unroll
            for (int i = 0; i < 4; i++)
#pragma unroll
                for (int j = 0; j < 2; j++) {
                    mma_bf16(accA[i][j], ah[i], bAh[j]);   // hi*hi
                    mma_bf16(accA[i][j], ah[i], bAl[j]);   // hi*lo
                    mma_bf16(accA[i][j], al[i], bAh[j]);   // lo*hi
                    mma_bf16(accX[i][j], ah[i], bXh[j]);
                    mma_bf16(accX[i][j], ah[i], bXl[j]);
                    mma_bf16(accX[i][j], al[i], bXh[j]);
                }
        }
    }

    // Epilogue: alpha = sigmoid(uA + b_alpha); c = (1-alpha)*tanh(uX + b_v)
#pragma unroll
    for (int i = 0; i < 4; i++)
#pragma unroll
        for (int j = 0; j < 2; j++) {
            const int mrow = m_base + wm + i * 16 + grp;
            const int ncol = n_base + wn + j * 8 + tig * 2;
            const float ba0 = b_alpha[ncol], ba1 = b_alpha[ncol + 1];
            const float bv0 = b_v[ncol],     bv1 = b_v[ncol + 1];
#pragma unroll
            for (int half = 0; half < 2; half++) {
                const int m = mrow + half * 8;
                float uA0 = accA[i][j][half * 2 + 0] + ba0;
                float uA1 = accA[i][j][half * 2 + 1] + ba1;
                float uX0 = accX[i][j][half * 2 + 0] + bv0;
                float uX1 = accX[i][j][half * 2 + 1] + bv1;
                float al0 = 1.0f / (1.0f + __expf(-uA0));
                float al1 = 1.0f / (1.0f + __expf(-uA1));
                float c0v = (1.0f - al0) * tanhf(uX0);
                float c1v = (1.0f - al1) * tanhf(uX1);
                g_ac[(size_t)m * D_DIM + ncol]     = make_float2(al0, c0v);
                g_ac[(size_t)m * D_DIM + ncol + 1] = make_float2(al1, c1v);
            }
        }
}

// ---------------- Sequential scan: independent per (b,d) column ------------------------
// h' = alpha*h + c * sigmoid(b_g - d_g*|h|) ;  out = h'^2 * sigmoid(h')
__global__ __launch_bounds__(128, 8)
void scan_kernel(const float* __restrict__ dgv, const float* __restrict__ bgv,
                 float* __restrict__ outs, float* __restrict__ hout, int writeH)
{
    const int S = B_DIM * D_DIM;   // 16384 columns
    const int j = blockIdx.x * blockDim.x + threadIdx.x;
    if (j >= S) return;
    const int dcol = j & (D_DIM - 1);
    const float dg  = dgv[dcol];
    const float nbg = -bgv[dcol];
    const float2* __restrict__ AC = g_ac;

    float h = 0.0f;
    if (writeH) hout[j] = 0.0f;

    constexpr int CH = 16;
    float2 ac0[CH], ac1[CH];
#pragma unroll
    for (int i = 0; i < CH; i++)
        ac0[i] = AC[(size_t)i * S + j];

    for (int t0 = 0; t0 < T_DIM; t0 += 2 * CH) {
        // prefetch chunk B
#pragma unroll
        for (int i = 0; i < CH; i++)
            ac1[i] = AC[(size_t)(t0 + CH + i) * S + j];
        // process chunk A
#pragma unroll
        for (int i = 0; i < CH; i++) {
            const int t = t0 + i;
            const float alpha = ac0[i].x, cf = ac0[i].y;
            const float earg = fmaf(dg, fabsf(h), nbg);            // d_g|h| - b_g
            const float g = __fdividef(1.0f, 1.0f + __expf(earg)); // sigmoid(b_g - d_g|h|)
            const float hn = fmaf(cf, g, alpha * h);
            const float sg = __fdividef(1.0f, 1.0f + __expf(-hn));
            outs[(size_t)t * S + j] = hn * hn * sg;
            if (writeH) hout[(size_t)(t + 1) * S + j] = hn;
            h = hn;
        }
        // prefetch next chunk A
        if (t0 + 2 * CH < T_DIM) {
#pragma unroll
            for (int i = 0; i < CH; i++)
                ac0[i] = AC[(size_t)(t0 + 2 * CH + i) * S + j];
        }
        // process chunk B
#pragma unroll
        for (int i = 0; i < CH; i++) {
            const int t = t0 + CH + i;
            const float alpha = ac1[i].x, cf = ac1[i].y;
            const float earg = fmaf(dg, fabsf(h), nbg);
            const float g = __fdividef(1.0f, 1.0f + __expf(earg));
            const float hn = fmaf(cf, g, alpha * h);
            const float sg = __fdividef(1.0f, 1.0f + __expf(-hn));
            outs[(size_t)t * S + j] = hn * hn * sg;
            if (writeH) hout[(size_t)(t + 1) * S + j] = hn;
            h = hn;
        }
    }
}

// ---------------- launch -----------------------------------------------------------------
extern "C" void kernel_launch(void* const* d_in, const int* in_sizes, int n_in,
                              void* d_out, int out_size)
{
    const float* x  = (const float*)d_in[0];   // [T,B,D]
    const float* Wa = (const float*)d_in[1];   // [D,D]
    const float* ba = (const float*)d_in[2];   // [D]
    const float* dg = (const float*)d_in[3];   // [D]
    const float* bg = (const float*)d_in[4];   // [D]
    const float* Wx = (const float*)d_in[5];   // [D,D]
    const float* bv = (const float*)d_in[6];   // [D]

    float* out  = (float*)d_out;
    float* outs = out;                               // [T,B,D]
    float* hout = out + (size_t)M_DIM * D_DIM;       // [T+1,B,D]
    const int writeH = (out_size > M_DIM * D_DIM) ? 1 : 0;

    dim3 grid(D_DIM / BN, M_DIM / BM);   // (16, 256), N fastest for x L2 reuse
    gemm2_kernel<<<grid, 256>>>(x, Wa, Wx, ba, bv);

    const int S = B_DIM * D_DIM;
    scan_kernel<<<S / 128, 128>>>(dg, bg, outs, hout, writeH);
}

// round 4
// speedup vs baseline: 1.4915x; 1.4915x over previous
#include <cuda_runtime.h>
#include <cuda_bf16.h>
#include <stdint.h>
#include <stddef.h>

// Problem dims (fixed by the reference)
#define T_DIM 2048
#define B_DIM 16
#define D_DIM 1024
#define M_DIM (T_DIM * B_DIM)   // 32768

// Scratch (static __device__; no cudaMalloc allowed)
__device__ float2 g_ac[(size_t)M_DIM * D_DIM];                 // {alpha, c}
__device__ __nv_bfloat16 gXh[(size_t)M_DIM * D_DIM];           // x hi
__device__ __nv_bfloat16 gXl[(size_t)M_DIM * D_DIM];           // x lo
__device__ __nv_bfloat16 gWh[(size_t)16 * 128 * D_DIM];        // remapped Wa|Wx hi
__device__ __nv_bfloat16 gWl[(size_t)16 * 128 * D_DIM];        // remapped Wa|Wx lo

// ===================== split helpers =====================
static __device__ __forceinline__ void split4(float4 v, uint32_t& h01, uint32_t& h23,
                                              uint32_t& l01, uint32_t& l23) {
    uint32_t b0 = __float_as_uint(v.x), b1 = __float_as_uint(v.y);
    uint32_t b2 = __float_as_uint(v.z), b3 = __float_as_uint(v.w);
    // hi = truncate-to-bf16 (exact split so lo is exactly representable)
    asm("prmt.b32 %0, %1, %2, 0x7632;" : "=r"(h01) : "r"(b0), "r"(b1));
    asm("prmt.b32 %0, %1, %2, 0x7632;" : "=r"(h23) : "r"(b2), "r"(b3));
    float l0 = v.x - __uint_as_float(b0 & 0xFFFF0000u);
    float l1 = v.y - __uint_as_float(b1 & 0xFFFF0000u);
    float l2 = v.z - __uint_as_float(b2 & 0xFFFF0000u);
    float l3 = v.w - __uint_as_float(b3 & 0xFFFF0000u);
    asm("cvt.rn.bf16x2.f32 %0, %1, %2;" : "=r"(l01) : "f"(l1), "f"(l0));
    asm("cvt.rn.bf16x2.f32 %0, %1, %2;" : "=r"(l23) : "f"(l3), "f"(l2));
}

__global__ void __launch_bounds__(256)
split_x_kernel(const float* __restrict__ x) {
    const size_t idx = (size_t)blockIdx.x * 256 + threadIdx.x;  // float4 index
    float4 v = ((const float4*)x)[idx];
    uint32_t h01, h23, l01, l23;
    split4(v, h01, h23, l01, l23);
    ((uint2*)gXh)[idx] = make_uint2(h01, h23);
    ((uint2*)gXl)[idx] = make_uint2(l01, l23);
}

// Remap weights: dest row (n>>6)*128 + m*64 + (n&63), m=0 -> Wa, m=1 -> Wx
__global__ void __launch_bounds__(256)
split_w_kernel(const float* __restrict__ Wa, const float* __restrict__ Wx) {
    const int e = blockIdx.x * 256 + threadIdx.x;   // float4 index over 2*1024*1024/4
    const int m = e >> 18;                           // 0: Wa, 1: Wx
    const int rem = e & 262143;
    const int n = rem >> 8;                          // source row
    const int c4 = rem & 255;                        // float4 col
    const float* src = m ? Wx : Wa;
    float4 v = ((const float4*)(src + (size_t)n * D_DIM))[c4];
    uint32_t h01, h23, l01, l23;
    split4(v, h01, h23, l01, l23);
    const size_t drow = (size_t)(n >> 6) * 128 + m * 64 + (n & 63);
    ((uint2*)gWh)[drow * 256 + c4] = make_uint2(h01, h23);
    ((uint2*)gWl)[drow * 256 + c4] = make_uint2(l01, l23);
}

// ===================== GEMM (mma.sync + cp.async + ldmatrix) =====================
// Per CTA: M=128 rows of x, N=64 output cols for BOTH matrices (B tile = Wa64|Wx64).
// 3-product split-bf16: acc += Ah*Bh + Ah*Bl + Al*Bh  (fp32 accum)
#define BK 64
#define ROWP 144                       // padded row pitch bytes (64 bf16 = 128B + 16B pad)
#define PART 18432                     // 128 rows * 144B
#define STAGE_BYTES (4 * PART)         // Ah | Al | Bh | Bl = 73728
#define NSTAGE 3
#define SMEM_DYN (NSTAGE * STAGE_BYTES)   // 221184

static __device__ __forceinline__ uint32_t smem_u32(const void* p) {
    uint32_t a;
    asm("{ .reg .u64 t; cvta.to.shared.u64 t, %1; cvt.u32.u64 %0, t; }" : "=r"(a) : "l"(p));
    return a;
}
static __device__ __forceinline__ void cp16(uint32_t dst, const void* src) {
    asm volatile("cp.async.cg.shared.global [%0], [%1], 16;" :: "r"(dst), "l"(src) : "memory");
}
#define CP_COMMIT() asm volatile("cp.async.commit_group;" ::: "memory")
#define CP_WAIT1()  asm volatile("cp.async.wait_group 1;" ::: "memory")
#define CP_WAIT0()  asm volatile("cp.async.wait_group 0;" ::: "memory")

#define LDSM4(R, A) \
    asm volatile("ldmatrix.sync.aligned.m8n8.x4.shared.b16 {%0,%1,%2,%3}, [%4];" \
        : "=r"((R)[0]), "=r"((R)[1]), "=r"((R)[2]), "=r"((R)[3]) : "r"(A))

static __device__ __forceinline__ void mma_bf16(float* c, const uint32_t* a, const uint32_t* b) {
    asm volatile(
        "mma.sync.aligned.m16n8k16.row.col.f32.bf16.bf16.f32 "
        "{%0,%1,%2,%3}, {%4,%5,%6,%7}, {%8,%9}, {%0,%1,%2,%3};\n"
        : "+f"(c[0]), "+f"(c[1]), "+f"(c[2]), "+f"(c[3])
        : "r"(a[0]), "r"(a[1]), "r"(a[2]), "r"(a[3]), "r"(b[0]), "r"(b[1]));
}

extern __shared__ char dsmem[];

__global__ void __launch_bounds__(256, 1)
gemm_mma(const float* __restrict__ ba, const float* __restrict__ bv)
{
    const int tid = threadIdx.x;
    const int warp = tid >> 5;
    const int lane = tid & 31;
    const int n_base = blockIdx.x * 64;
    const int m_base = blockIdx.y * 128;
    const int wrow_base = blockIdx.x * 128;   // remapped weight row base

    const uint32_t sb = smem_u32(dsmem);

    // --- cp.async tile loader: 4 arrays x 1024 16B-chunks, 4 chunks/thread/array ---
#define ISSUE_LOAD(KK, SBASE) do {                                                    \
    const uint32_t sAh = (SBASE);                                                     \
    _Pragma("unroll")                                                                 \
    for (int q = 0; q < 4; q++) {                                                     \
        const int idx = tid + 256 * q;                                                \
        const int row = idx >> 3;                                                     \
        const int c16 = idx & 7;                                                      \
        const size_t xo = ((size_t)(m_base + row) * D_DIM + (KK) + c16 * 8) * 2;      \
        const size_t wo = ((size_t)(wrow_base + row) * D_DIM + (KK) + c16 * 8) * 2;   \
        const uint32_t so = (uint32_t)(row * ROWP + c16 * 16);                        \
        cp16(sAh + so,            (const char*)gXh + xo);                             \
        cp16(sAh + PART + so,     (const char*)gXl + xo);                             \
        cp16(sAh + 2 * PART + so, (const char*)gWh + wo);                             \
        cp16(sAh + 3 * PART + so, (const char*)gWl + wo);                             \
    }                                                                                 \
    CP_COMMIT();                                                                      \
} while (0)

    // warp tiling: wm in {0,64}, wn in {0,16,32,48}
    const int wm = (warp >> 2) * 64;
    const int wn = (warp & 3) * 16;
    const int grp = lane >> 2;
    const int tig = lane & 3;

    float accA[4][2][4], accX[4][2][4];
#pragma unroll
    for (int i = 0; i < 4; i++)
#pragma unroll
        for (int j = 0; j < 2; j++)
#pragma unroll
            for (int r = 0; r < 4; r++) { accA[i][j][r] = 0.f; accX[i][j][r] = 0.f; }

    // ldmatrix per-lane address components
    const int rowA = ((lane >> 3) & 1) * 8 + (lane & 7);    // + khalfA selects k+8 half
    const int khalfA = lane >> 4;
    const int rowB = ((lane >> 4) << 3) + (lane & 7);
    const int khalfB = (lane >> 3) & 1;

    ISSUE_LOAD(0, sb);
    ISSUE_LOAD(BK, sb + STAGE_BYTES);

    for (int kc = 0; kc < 16; kc++) {
        CP_WAIT1();
        __syncthreads();
        if (kc + 2 < 16)
            ISSUE_LOAD((kc + 2) * BK, sb + ((kc + 2) % NSTAGE) * STAGE_BYTES);

        const uint32_t stage = sb + (kc % NSTAGE) * STAGE_BYTES;
        const uint32_t aBase = stage + (uint32_t)((wm + rowA) * ROWP + khalfA * 16);
        const uint32_t bBase = stage + 2 * PART + (uint32_t)((wn + rowB) * ROWP + khalfB * 16);

#pragma unroll
        for (int ks = 0; ks < 4; ks++) {
            const uint32_t ka = aBase + ks * 32;
            const uint32_t kb = bBase + ks * 32;
            uint32_t ah[4][4], al[4][4];
#pragma unroll
            for (int i = 0; i < 4; i++) {
                LDSM4(ah[i], ka + i * (16 * ROWP));
                LDSM4(al[i], ka + PART + i * (16 * ROWP));
            }
            uint32_t bAh[4], bAl[4], bXh[4], bXl[4];
            LDSM4(bAh, kb);                        // Wa rows (0..63)
            LDSM4(bAl, kb + PART);
            LDSM4(bXh, kb + 64 * ROWP);            // Wx rows (64..127)
            LDSM4(bXl, kb + PART + 64 * ROWP);
#pragma unroll
            for (int i = 0; i < 4; i++)
#pragma unroll
                for (int j = 0; j < 2; j++) {
                    mma_bf16(accA[i][j], ah[i], &bAh[j * 2]);
                    mma_bf16(accA[i][j], ah[i], &bAl[j * 2]);
                    mma_bf16(accA[i][j], al[i], &bAh[j * 2]);
                    mma_bf16(accX[i][j], ah[i], &bXh[j * 2]);
                    mma_bf16(accX[i][j], ah[i], &bXl[j * 2]);
                    mma_bf16(accX[i][j], al[i], &bXh[j * 2]);
                }
        }
    }
#undef ISSUE_LOAD
    CP_WAIT0();

    // Epilogue: alpha = sigmoid(uA + ba); c = (1-alpha)*tanh(uX + bv)
#pragma unroll
    for (int i = 0; i < 4; i++)
#pragma unroll
        for (int j = 0; j < 2; j++) {
            const int mrow = m_base + wm + i * 16 + grp;
            const int ncol = n_base + wn + j * 8 + tig * 2;
            const float ba0 = ba[ncol], ba1 = ba[ncol + 1];
            const float bv0 = bv[ncol], bv1 = bv[ncol + 1];
#pragma unroll
            for (int half = 0; half < 2; half++) {
                const int m = mrow + half * 8;
                float uA0 = accA[i][j][half * 2 + 0] + ba0;
                float uA1 = accA[i][j][half * 2 + 1] + ba1;
                float uX0 = accX[i][j][half * 2 + 0] + bv0;
                float uX1 = accX[i][j][half * 2 + 1] + bv1;
                float al0 = 1.0f / (1.0f + __expf(-uA0));
                float al1 = 1.0f / (1.0f + __expf(-uA1));
                float c0v = (1.0f - al0) * tanhf(uX0);
                float c1v = (1.0f - al1) * tanhf(uX1);
                g_ac[(size_t)m * D_DIM + ncol]     = make_float2(al0, c0v);
                g_ac[(size_t)m * D_DIM + ncol + 1] = make_float2(al1, c1v);
            }
        }
}

// ===================== Sequential scan (deeper prefetch, full reg budget) =====================
__global__ void scan_kernel(const float* __restrict__ dgv, const float* __restrict__ bgv,
                            float* __restrict__ outs, float* __restrict__ hout, int writeH)
{
    const int S = B_DIM * D_DIM;   // 16384 columns
    const int j = blockIdx.x * blockDim.x + threadIdx.x;
    if (j >= S) return;
    const int dcol = j & (D_DIM - 1);
    const float dg  = dgv[dcol];
    const float nbg = -bgv[dcol];
    const float2* __restrict__ AC = g_ac;

    float h = 0.0f;
    if (writeH) hout[j] = 0.0f;

    constexpr int CH = 32;
    float2 ac0[CH], ac1[CH];
#pragma unroll
    for (int i = 0; i < CH; i++)
        ac0[i] = AC[(size_t)i * S + j];

    for (int t0 = 0; t0 < T_DIM; t0 += 2 * CH) {
#pragma unroll
        for (int i = 0; i < CH; i++)
            ac1[i] = AC[(size_t)(t0 + CH + i) * S + j];
#pragma unroll
        for (int i = 0; i < CH; i++) {
            const int t = t0 + i;
            const float alpha = ac0[i].x, cf = ac0[i].y;
            const float earg = fmaf(dg, fabsf(h), nbg);
            const float g = __fdividef(1.0f, 1.0f + __expf(earg));
            const float hn = fmaf(cf, g, alpha * h);
            const float sg = __fdividef(1.0f, 1.0f + __expf(-hn));
            outs[(size_t)t * S + j] = hn * hn * sg;
            if (writeH) hout[(size_t)(t + 1) * S + j] = hn;
            h = hn;
        }
        if (t0 + 2 * CH < T_DIM) {
#pragma unroll
            for (int i = 0; i < CH; i++)
                ac0[i] = AC[(size_t)(t0 + 2 * CH + i) * S + j];
        }
#pragma unroll
        for (int i = 0; i < CH; i++) {
            const int t = t0 + CH + i;
            const float alpha = ac1[i].x, cf = ac1[i].y;
            const float earg = fmaf(dg, fabsf(h), nbg);
            const float g = __fdividef(1.0f, 1.0f + __expf(earg));
            const float hn = fmaf(cf, g, alpha * h);
            const float sg = __fdividef(1.0f, 1.0f + __expf(-hn));
            outs[(size_t)t * S + j] = hn * hn * sg;
            if (writeH) hout[(size_t)(t + 1) * S + j] = hn;
            h = hn;
        }
    }
}

// ========================= launch =========================
extern "C" void kernel_launch(void* const* d_in, const int* in_sizes, int n_in,
                              void* d_out, int out_size)
{
    const float* x  = (const float*)d_in[0];
    const float* Wa = (const float*)d_in[1];
    const float* ba = (const float*)d_in[2];
    const float* dg = (const float*)d_in[3];
    const float* bg = (const float*)d_in[4];
    const float* Wx = (const float*)d_in[5];
    const float* bv = (const float*)d_in[6];

    float* out  = (float*)d_out;
    float* outs = out;
    float* hout = out + (size_t)M_DIM * D_DIM;
    const int writeH = (out_size > M_DIM * D_DIM) ? 1 : 0;

    // Precompute: split x and remap+split weights into bf16 hi/lo
    split_x_kernel<<<(int)(((size_t)M_DIM * D_DIM / 4) / 256), 256>>>(x);
    split_w_kernel<<<(2 * D_DIM * D_DIM / 4) / 256, 256>>>(Wa, Wx);

    static int smem_set = 0;
    if (!smem_set) {
        cudaFuncSetAttribute(gemm_mma, cudaFuncAttributeMaxDynamicSharedMemorySize, SMEM_DYN);
        smem_set = 1;
    }
    dim3 grid(D_DIM / 64, M_DIM / 128);   // (16, 256), N fastest for x L2 reuse
    gemm_mma<<<grid, 256, SMEM_DYN>>>(ba, bv);

    scan_kernel<<<256, 64>>>(dg, bg, outs, hout, writeH);
}

// round 5
// speedup vs baseline: 1.9107x; 1.2811x over previous
#include <cuda_runtime.h>
#include <cuda_fp16.h>
#include <stdint.h>
#include <stddef.h>

// Problem dims (fixed by the reference)
#define T_DIM 2048
#define B_DIM 16
#define D_DIM 1024
#define M_DIM (T_DIM * B_DIM)   // 32768

// Scratch (static __device__; no cudaMalloc allowed)
__device__ float2 g_ac[(size_t)M_DIM * D_DIM];         // {alpha, c}
__device__ __half gXh[(size_t)M_DIM * D_DIM];          // x hi (fp16 rn)
__device__ __half gXl[(size_t)M_DIM * D_DIM];          // x residual (fp16 rn)
__device__ __half gW[(size_t)16 * 128 * D_DIM];        // remapped Wa|Wx, single fp16

// ===================== split helpers =====================
static __device__ __forceinline__ uint32_t pack2(__half a, __half b) {
    return (uint32_t)__half_as_ushort(a) | ((uint32_t)__half_as_ushort(b) << 16);
}

__global__ void __launch_bounds__(256)
split_x_kernel(const float* __restrict__ x) {
    const size_t idx = (size_t)blockIdx.x * 256 + threadIdx.x;  // float4 index
    float4 v = ((const float4*)x)[idx];
    __half h0 = __float2half_rn(v.x);
    __half h1 = __float2half_rn(v.y);
    __half h2 = __float2half_rn(v.z);
    __half h3 = __float2half_rn(v.w);
    __half l0 = __float2half_rn(v.x - __half2float(h0));
    __half l1 = __float2half_rn(v.y - __half2float(h1));
    __half l2 = __float2half_rn(v.z - __half2float(h2));
    __half l3 = __float2half_rn(v.w - __half2float(h3));
    ((uint2*)gXh)[idx] = make_uint2(pack2(h0, h1), pack2(h2, h3));
    ((uint2*)gXl)[idx] = make_uint2(pack2(l0, l1), pack2(l2, l3));
}

// Remap weights: dest row (n>>6)*128 + m*64 + (n&63), m=0 -> Wa, m=1 -> Wx
__global__ void __launch_bounds__(256)
split_w_kernel(const float* __restrict__ Wa, const float* __restrict__ Wx) {
    const int e = blockIdx.x * 256 + threadIdx.x;   // float4 index over 2*1024*1024/4
    const int m = e >> 18;                           // 0: Wa, 1: Wx
    const int rem = e & 262143;
    const int n = rem >> 8;                          // source row
    const int c4 = rem & 255;                        // float4 col
    const float* src = m ? Wx : Wa;
    float4 v = ((const float4*)(src + (size_t)n * D_DIM))[c4];
    __half h0 = __float2half_rn(v.x);
    __half h1 = __float2half_rn(v.y);
    __half h2 = __float2half_rn(v.z);
    __half h3 = __float2half_rn(v.w);
    const size_t drow = (size_t)(n >> 6) * 128 + m * 64 + (n & 63);
    ((uint2*)gW)[drow * 256 + c4] = make_uint2(pack2(h0, h1), pack2(h2, h3));
}

// ===================== GEMM (mma.sync fp16 + cp.async + ldmatrix) =====================
// Per CTA: M=128 rows of x, N=64 output cols for BOTH matrices (B tile = Wa64|Wx64).
// 2-product A-split: acc += Ah*W + Al*W  (fp32 accum; W single-rounded fp16)
#define BK 64
#define ROWP 144                       // padded row pitch bytes (64 fp16 = 128B + 16B pad)
#define PART 18432                     // 128 rows * 144B
#define STAGE_BYTES (3 * PART)         // Ah | Al | W = 55296
#define NSTAGE 3
#define SMEM_DYN (NSTAGE * STAGE_BYTES)   // 165888

static __device__ __forceinline__ uint32_t smem_u32(const void* p) {
    uint32_t a;
    asm("{ .reg .u64 t; cvta.to.shared.u64 t, %1; cvt.u32.u64 %0, t; }" : "=r"(a) : "l"(p));
    return a;
}
static __device__ __forceinline__ void cp16(uint32_t dst, const void* src) {
    asm volatile("cp.async.cg.shared.global [%0], [%1], 16;" :: "r"(dst), "l"(src) : "memory");
}
#define CP_COMMIT() asm volatile("cp.async.commit_group;" ::: "memory")
#define CP_WAIT1()  asm volatile("cp.async.wait_group 1;" ::: "memory")
#define CP_WAIT0()  asm volatile("cp.async.wait_group 0;" ::: "memory")

#define LDSM4(R, A) \
    asm volatile("ldmatrix.sync.aligned.m8n8.x4.shared.b16 {%0,%1,%2,%3}, [%4];" \
        : "=r"((R)[0]), "=r"((R)[1]), "=r"((R)[2]), "=r"((R)[3]) : "r"(A))

static __device__ __forceinline__ void mma_fp16(float* c, const uint32_t* a, const uint32_t* b) {
    asm volatile(
        "mma.sync.aligned.m16n8k16.row.col.f32.f16.f16.f32 "
        "{%0,%1,%2,%3}, {%4,%5,%6,%7}, {%8,%9}, {%0,%1,%2,%3};\n"
        : "+f"(c[0]), "+f"(c[1]), "+f"(c[2]), "+f"(c[3])
        : "r"(a[0]), "r"(a[1]), "r"(a[2]), "r"(a[3]), "r"(b[0]), "r"(b[1]));
}

extern __shared__ char dsmem[];

__global__ void __launch_bounds__(256, 1)
gemm_mma(const float* __restrict__ ba, const float* __restrict__ bv)
{
    const int tid = threadIdx.x;
    const int warp = tid >> 5;
    const int lane = tid & 31;
    const int n_base = blockIdx.x * 64;
    const int m_base = blockIdx.y * 128;
    const int wrow_base = blockIdx.x * 128;   // remapped weight row base

    const uint32_t sb = smem_u32(dsmem);

    // --- cp.async tile loader: 3 arrays x 1024 16B-chunks, 4 chunks/thread/array ---
#define ISSUE_LOAD(KK, SBASE) do {                                                    \
    const uint32_t sAh = (SBASE);                                                     \
    _Pragma("unroll")                                                                 \
    for (int q = 0; q < 4; q++) {                                                     \
        const int idx = tid + 256 * q;                                                \
        const int row = idx >> 3;                                                     \
        const int c16 = idx & 7;                                                      \
        const size_t xo = ((size_t)(m_base + row) * D_DIM + (KK) + c16 * 8) * 2;      \
        const size_t wo = ((size_t)(wrow_base + row) * D_DIM + (KK) + c16 * 8) * 2;   \
        const uint32_t so = (uint32_t)(row * ROWP + c16 * 16);                        \
        cp16(sAh + so,            (const char*)gXh + xo);                             \
        cp16(sAh + PART + so,     (const char*)gXl + xo);                             \
        cp16(sAh + 2 * PART + so, (const char*)gW  + wo);                             \
    }                                                                                 \
    CP_COMMIT();                                                                      \
} while (0)

    // warp tiling: wm in {0,64}, wn in {0,16,32,48}
    const int wm = (warp >> 2) * 64;
    const int wn = (warp & 3) * 16;
    const int grp = lane >> 2;
    const int tig = lane & 3;

    float accA[4][2][4], accX[4][2][4];
#pragma unroll
    for (int i = 0; i < 4; i++)
#pragma unroll
        for (int j = 0; j < 2; j++)
#pragma unroll
            for (int r = 0; r < 4; r++) { accA[i][j][r] = 0.f; accX[i][j][r] = 0.f; }

    // ldmatrix per-lane address components
    const int rowA = ((lane >> 3) & 1) * 8 + (lane & 7);
    const int khalfA = lane >> 4;
    const int rowB = ((lane >> 4) << 3) + (lane & 7);
    const int khalfB = (lane >> 3) & 1;

    ISSUE_LOAD(0, sb);
    ISSUE_LOAD(BK, sb + STAGE_BYTES);

    for (int kc = 0; kc < 16; kc++) {
        CP_WAIT1();
        __syncthreads();
        if (kc + 2 < 16)
            ISSUE_LOAD((kc + 2) * BK, sb + ((kc + 2) % NSTAGE) * STAGE_BYTES);

        const uint32_t stage = sb + (kc % NSTAGE) * STAGE_BYTES;
        const uint32_t aBase = stage + (uint32_t)((wm + rowA) * ROWP + khalfA * 16);
        const uint32_t bBase = stage + 2 * PART + (uint32_t)((wn + rowB) * ROWP + khalfB * 16);

#pragma unroll
        for (int ks = 0; ks < 4; ks++) {
            const uint32_t ka = aBase + ks * 32;
            const uint32_t kb = bBase + ks * 32;
            uint32_t ah[4][4], al[4][4];
#pragma unroll
            for (int i = 0; i < 4; i++) {
                LDSM4(ah[i], ka + i * (16 * ROWP));
                LDSM4(al[i], ka + PART + i * (16 * ROWP));
            }
            uint32_t bA[4], bX[4];
            LDSM4(bA, kb);                         // Wa rows (0..63)
            LDSM4(bX, kb + 64 * ROWP);             // Wx rows (64..127)
#pragma unroll
            for (int i = 0; i < 4; i++)
#pragma unroll
                for (int j = 0; j < 2; j++) {
                    mma_fp16(accA[i][j], ah[i], &bA[j * 2]);
                    mma_fp16(accA[i][j], al[i], &bA[j * 2]);
                    mma_fp16(accX[i][j], ah[i], &bX[j * 2]);
                    mma_fp16(accX[i][j], al[i], &bX[j * 2]);
                }
        }
    }
#undef ISSUE_LOAD
    CP_WAIT0();

    // Epilogue: alpha = sigmoid(uA + ba); c = (1-alpha)*tanh(uX + bv)
#pragma unroll
    for (int i = 0; i < 4; i++)
#pragma unroll
        for (int j = 0; j < 2; j++) {
            const int mrow = m_base + wm + i * 16 + grp;
            const int ncol = n_base + wn + j * 8 + tig * 2;
            const float ba0 = ba[ncol], ba1 = ba[ncol + 1];
            const float bv0 = bv[ncol], bv1 = bv[ncol + 1];
#pragma unroll
            for (int half = 0; half < 2; half++) {
                const int m = mrow + half * 8;
                float uA0 = accA[i][j][half * 2 + 0] + ba0;
                float uA1 = accA[i][j][half * 2 + 1] + ba1;
                float uX0 = accX[i][j][half * 2 + 0] + bv0;
                float uX1 = accX[i][j][half * 2 + 1] + bv1;
                float al0 = 1.0f / (1.0f + __expf(-uA0));
                float al1 = 1.0f / (1.0f + __expf(-uA1));
                float c0v = (1.0f - al0) * tanhf(uX0);
                float c1v = (1.0f - al1) * tanhf(uX1);
                g_ac[(size_t)m * D_DIM + ncol]     = make_float2(al0, c0v);
                g_ac[(size_t)m * D_DIM + ncol + 1] = make_float2(al1, c1v);
            }
        }
}

// ===================== Sequential scan (unchanged from passing R4) =====================
__global__ void scan_kernel(const float* __restrict__ dgv, const float* __restrict__ bgv,
                            float* __restrict__ outs, float* __restrict__ hout, int writeH)
{
    const int S = B_DIM * D_DIM;   // 16384 columns
    const int j = blockIdx.x * blockDim.x + threadIdx.x;
    if (j >= S) return;
    const int dcol = j & (D_DIM - 1);
    const float dg  = dgv[dcol];
    const float nbg = -bgv[dcol];
    const float2* __restrict__ AC = g_ac;

    float h = 0.0f;
    if (writeH) hout[j] = 0.0f;

    constexpr int CH = 32;
    float2 ac0[CH], ac1[CH];
#pragma unroll
    for (int i = 0; i < CH; i++)
        ac0[i] = AC[(size_t)i * S + j];

    for (int t0 = 0; t0 < T_DIM; t0 += 2 * CH) {
#pragma unroll
        for (int i = 0; i < CH; i++)
            ac1[i] = AC[(size_t)(t0 + CH + i) * S + j];
#pragma unroll
        for (int i = 0; i < CH; i++) {
            const int t = t0 + i;
            const float alpha = ac0[i].x, cf = ac0[i].y;
            const float earg = fmaf(dg, fabsf(h), nbg);
            const float g = __fdividef(1.0f, 1.0f + __expf(earg));
            const float hn = fmaf(cf, g, alpha * h);
            const float sg = __fdividef(1.0f, 1.0f + __expf(-hn));
            outs[(size_t)t * S + j] = hn * hn * sg;
            if (writeH) hout[(size_t)(t + 1) * S + j] = hn;
            h = hn;
        }
        if (t0 + 2 * CH < T_DIM) {
#pragma unroll
            for (int i = 0; i < CH; i++)
                ac0[i] = AC[(size_t)(t0 + 2 * CH + i) * S + j];
        }
#pragma unroll
        for (int i = 0; i < CH; i++) {
            const int t = t0 + CH + i;
            const float alpha = ac1[i].x, cf = ac1[i].y;
            const float earg = fmaf(dg, fabsf(h), nbg);
            const float g = __fdividef(1.0f, 1.0f + __expf(earg));
            const float hn = fmaf(cf, g, alpha * h);
            const float sg = __fdividef(1.0f, 1.0f + __expf(-hn));
            outs[(size_t)t * S + j] = hn * hn * sg;
            if (writeH) hout[(size_t)(t + 1) * S + j] = hn;
            h = hn;
        }
    }
}

// ========================= launch =========================
extern "C" void kernel_launch(void* const* d_in, const int* in_sizes, int n_in,
                              void* d_out, int out_size)
{
    const float* x  = (const float*)d_in[0];
    const float* Wa = (const float*)d_in[1];
    const float* ba = (const float*)d_in[2];
    const float* dg = (const float*)d_in[3];
    const float* bg = (const float*)d_in[4];
    const float* Wx = (const float*)d_in[5];
    const float* bv = (const float*)d_in[6];

    float* out  = (float*)d_out;
    float* outs = out;
    float* hout = out + (size_t)M_DIM * D_DIM;
    const int writeH = (out_size > M_DIM * D_DIM) ? 1 : 0;

    // Precompute: split x into fp16 hi/lo; remap weights into single fp16
    split_x_kernel<<<(int)(((size_t)M_DIM * D_DIM / 4) / 256), 256>>>(x);
    split_w_kernel<<<(2 * D_DIM * D_DIM / 4) / 256, 256>>>(Wa, Wx);

    static int smem_set = 0;
    if (!smem_set) {
        cudaFuncSetAttribute(gemm_mma, cudaFuncAttributeMaxDynamicSharedMemorySize, SMEM_DYN);
        smem_set = 1;
    }
    dim3 grid(D_DIM / 64, M_DIM / 128);   // (16, 256), N fastest for x L2 reuse
    gemm_mma<<<grid, 256, SMEM_DYN>>>(ba, bv);

    scan_kernel<<<256, 64>>>(dg, bg, outs, hout, writeH);
}

// round 6
// speedup vs baseline: 1.9665x; 1.0292x over previous
#include <cuda_runtime.h>
#include <cuda_fp16.h>
#include <stdint.h>
#include <stddef.h>

// Problem dims (fixed by the reference)
#define T_DIM 2048
#define B_DIM 16
#define D_DIM 1024
#define M_DIM (T_DIM * B_DIM)   // 32768

// Scratch (static __device__; no cudaMalloc allowed)
__device__ float2 g_ac[(size_t)M_DIM * D_DIM];         // {alpha, c}
__device__ __half gXh[(size_t)M_DIM * D_DIM];          // x (fp16 rn)
__device__ __half gW[(size_t)16 * 128 * D_DIM];        // remapped Wa|Wx, fp16

// ===================== common helpers =====================
static __device__ __forceinline__ uint32_t pack2(__half a, __half b) {
    return (uint32_t)__half_as_ushort(a) | ((uint32_t)__half_as_ushort(b) << 16);
}
static __device__ __forceinline__ uint32_t smem_u32(const void* p) {
    uint32_t a;
    asm("{ .reg .u64 t; cvta.to.shared.u64 t, %1; cvt.u32.u64 %0, t; }" : "=r"(a) : "l"(p));
    return a;
}
static __device__ __forceinline__ void cp16(uint32_t dst, const void* src) {
    asm volatile("cp.async.cg.shared.global [%0], [%1], 16;" :: "r"(dst), "l"(src) : "memory");
}
#define CP_COMMIT() asm volatile("cp.async.commit_group;" ::: "memory")
#define CP_WAIT1()  asm volatile("cp.async.wait_group 1;" ::: "memory")
#define CP_WAIT0()  asm volatile("cp.async.wait_group 0;" ::: "memory")
#define CP_WAIT5()  asm volatile("cp.async.wait_group 5;" ::: "memory")

// ===================== precompute kernels =====================
__global__ void __launch_bounds__(256)
split_x_kernel(const float* __restrict__ x) {
    const size_t idx = (size_t)blockIdx.x * 256 + threadIdx.x;  // float4 index
    float4 v = ((const float4*)x)[idx];
    ((uint2*)gXh)[idx] = make_uint2(
        pack2(__float2half_rn(v.x), __float2half_rn(v.y)),
        pack2(__float2half_rn(v.z), __float2half_rn(v.w)));
}

// Remap weights: dest row (n>>6)*128 + m*64 + (n&63), m=0 -> Wa, m=1 -> Wx
__global__ void __launch_bounds__(256)
split_w_kernel(const float* __restrict__ Wa, const float* __restrict__ Wx) {
    const int e = blockIdx.x * 256 + threadIdx.x;   // float4 index over 2*1024*1024/4
    const int m = e >> 18;                           // 0: Wa, 1: Wx
    const int rem = e & 262143;
    const int n = rem >> 8;                          // source row
    const int c4 = rem & 255;                        // float4 col
    const float* src = m ? Wx : Wa;
    float4 v = ((const float4*)(src + (size_t)n * D_DIM))[c4];
    const size_t drow = (size_t)(n >> 6) * 128 + m * 64 + (n & 63);
    ((uint2*)gW)[drow * 256 + c4] = make_uint2(
        pack2(__float2half_rn(v.x), __float2half_rn(v.y)),
        pack2(__float2half_rn(v.z), __float2half_rn(v.w)));
}

// ===================== GEMM (fp16 mma.sync, single product) =====================
// Per CTA: M=128 rows of x, N=64 output cols for BOTH matrices (B tile = Wa64|Wx64).
#define BK 64
#define ROWP 144                       // padded row pitch bytes (64 fp16 = 128B + 16B pad)
#define PART 18432                     // 128 rows * 144B
#define STAGE_BYTES (2 * PART)         // A | W = 36864
#define NSTAGE 3
#define SMEM_DYN (NSTAGE * STAGE_BYTES)   // 110592

#define LDSM4(R, A) \
    asm volatile("ldmatrix.sync.aligned.m8n8.x4.shared.b16 {%0,%1,%2,%3}, [%4];" \
        : "=r"((R)[0]), "=r"((R)[1]), "=r"((R)[2]), "=r"((R)[3]) : "r"(A))

static __device__ __forceinline__ void mma_fp16(float* c, const uint32_t* a, const uint32_t* b) {
    asm volatile(
        "mma.sync.aligned.m16n8k16.row.col.f32.f16.f16.f32 "
        "{%0,%1,%2,%3}, {%4,%5,%6,%7}, {%8,%9}, {%0,%1,%2,%3};\n"
        : "+f"(c[0]), "+f"(c[1]), "+f"(c[2]), "+f"(c[3])
        : "r"(a[0]), "r"(a[1]), "r"(a[2]), "r"(a[3]), "r"(b[0]), "r"(b[1]));
}

extern __shared__ char dsmem[];

__global__ void __launch_bounds__(256, 1)
gemm_mma(const float* __restrict__ ba, const float* __restrict__ bv)
{
    const int tid = threadIdx.x;
    const int warp = tid >> 5;
    const int lane = tid & 31;
    const int n_base = blockIdx.x * 64;
    const int m_base = blockIdx.y * 128;
    const int wrow_base = blockIdx.x * 128;   // remapped weight row base

    const uint32_t sb = smem_u32(dsmem);

    // --- cp.async tile loader: 2 arrays x 1024 16B-chunks, 4 chunks/thread/array ---
#define ISSUE_LOAD(KK, SBASE) do {                                                    \
    const uint32_t sA = (SBASE);                                                      \
    _Pragma("unroll")                                                                 \
    for (int q = 0; q < 4; q++) {                                                     \
        const int idx = tid + 256 * q;                                                \
        const int row = idx >> 3;                                                     \
        const int c16 = idx & 7;                                                      \
        const size_t xo = ((size_t)(m_base + row) * D_DIM + (KK) + c16 * 8) * 2;      \
        const size_t wo = ((size_t)(wrow_base + row) * D_DIM + (KK) + c16 * 8) * 2;   \
        const uint32_t so = (uint32_t)(row * ROWP + c16 * 16);                        \
        cp16(sA + so,        (const char*)gXh + xo);                                  \
        cp16(sA + PART + so, (const char*)gW  + wo);                                  \
    }                                                                                 \
    CP_COMMIT();                                                                      \
} while (0)

    // warp tiling: wm in {0,64}, wn in {0,16,32,48}
    const int wm = (warp >> 2) * 64;
    const int wn = (warp & 3) * 16;
    const int grp = lane >> 2;
    const int tig = lane & 3;

    float accA[4][2][4], accX[4][2][4];
#pragma unroll
    for (int i = 0; i < 4; i++)
#pragma unroll
        for (int j = 0; j < 2; j++)
#pragma unroll
            for (int r = 0; r < 4; r++) { accA[i][j][r] = 0.f; accX[i][j][r] = 0.f; }

    // ldmatrix per-lane address components
    const int rowA = ((lane >> 3) & 1) * 8 + (lane & 7);
    const int khalfA = lane >> 4;
    const int rowB = ((lane >> 4) << 3) + (lane & 7);
    const int khalfB = (lane >> 3) & 1;

    ISSUE_LOAD(0, sb);
    ISSUE_LOAD(BK, sb + STAGE_BYTES);

    for (int kc = 0; kc < 16; kc++) {
        CP_WAIT1();
        __syncthreads();
        if (kc + 2 < 16)
            ISSUE_LOAD((kc + 2) * BK, sb + ((kc + 2) % NSTAGE) * STAGE_BYTES);

        const uint32_t stage = sb + (kc % NSTAGE) * STAGE_BYTES;
        const uint32_t aBase = stage + (uint32_t)((wm + rowA) * ROWP + khalfA * 16);
        const uint32_t bBase = stage + PART + (uint32_t)((wn + rowB) * ROWP + khalfB * 16);

#pragma unroll
        for (int ks = 0; ks < 4; ks++) {
            const uint32_t ka = aBase + ks * 32;
            const uint32_t kb = bBase + ks * 32;
            uint32_t ah[4][4];
#pragma unroll
            for (int i = 0; i < 4; i++)
                LDSM4(ah[i], ka + i * (16 * ROWP));
            uint32_t bA[4], bX[4];
            LDSM4(bA, kb);                         // Wa rows (0..63)
            LDSM4(bX, kb + 64 * ROWP);             // Wx rows (64..127)
#pragma unroll
            for (int i = 0; i < 4; i++)
#pragma unroll
                for (int j = 0; j < 2; j++) {
                    mma_fp16(accA[i][j], ah[i], &bA[j * 2]);
                    mma_fp16(accX[i][j], ah[i], &bX[j * 2]);
                }
        }
    }
#undef ISSUE_LOAD
    CP_WAIT0();

    // Epilogue: alpha = sigmoid(uA + ba); c = (1-alpha)*tanh(uX + bv)
#pragma unroll
    for (int i = 0; i < 4; i++)
#pragma unroll
        for (int j = 0; j < 2; j++) {
            const int mrow = m_base + wm + i * 16 + grp;
            const int ncol = n_base + wn + j * 8 + tig * 2;
            const float ba0 = ba[ncol], ba1 = ba[ncol + 1];
            const float bv0 = bv[ncol], bv1 = bv[ncol + 1];
#pragma unroll
            for (int half = 0; half < 2; half++) {
                const int m = mrow + half * 8;
                float uA0 = accA[i][j][half * 2 + 0] + ba0;
                float uA1 = accA[i][j][half * 2 + 1] + ba1;
                float uX0 = accX[i][j][half * 2 + 0] + bv0;
                float uX1 = accX[i][j][half * 2 + 1] + bv1;
                float al0 = 1.0f / (1.0f + __expf(-uA0));
                float al1 = 1.0f / (1.0f + __expf(-uA1));
                float c0v = (1.0f - al0) * tanhf(uX0);
                float c1v = (1.0f - al1) * tanhf(uX1);
                g_ac[(size_t)m * D_DIM + ncol]     = make_float2(al0, c0v);
                g_ac[(size_t)m * D_DIM + ncol + 1] = make_float2(al1, c1v);
            }
        }
}

// ===================== Sequential scan: cp.async deep pipeline =====================
// 6-stage x 16-step smem ring per block (48 KB). Same math/order as the passing R4/R5 scan.
#define SNB 6
#define SCH 16

__global__ void __launch_bounds__(64)
scan_kernel(const float* __restrict__ dgv, const float* __restrict__ bgv,
            float* __restrict__ outs, float* __restrict__ hout, int writeH)
{
    __shared__ float2 sbuf[SNB][SCH][64];
    const int S = B_DIM * D_DIM;   // 16384 columns
    const int tid = threadIdx.x;
    const int j0 = blockIdx.x * 64;
    const int j = j0 + tid;
    const int dcol = j & (D_DIM - 1);
    const float dg  = dgv[dcol];
    const float nbg = -bgv[dcol];

#define SC_ISSUE(slot, t0) do {                                                  \
    _Pragma("unroll")                                                            \
    for (int q = 0; q < 8; q++) {                                                \
        const int idx = tid + 64 * q;                                            \
        const int row = idx >> 5;        /* 0..15 */                             \
        const int ch  = idx & 31;        /* 0..31 (16B chunks) */                \
        cp16(smem_u32(&sbuf[slot][row][ch * 2]),                                 \
             (const char*)&g_ac[(size_t)((t0) + row) * S + j0 + ch * 2]);        \
    }                                                                            \
    CP_COMMIT();                                                                 \
} while (0)

    float h = 0.0f;
    if (writeH) hout[j] = 0.0f;

#pragma unroll
    for (int s = 0; s < SNB; s++)
        SC_ISSUE(s, s * SCH);

    for (int k = 0; k < T_DIM / SCH; k++) {
        CP_WAIT5();
        __syncthreads();
        const int slot = k % SNB;
#pragma unroll
        for (int i = 0; i < SCH; i++) {
            const float2 ac = sbuf[slot][i][tid];
            const int t = k * SCH + i;
            const float alpha = ac.x, cf = ac.y;
            const float earg = fmaf(dg, fabsf(h), nbg);            // d_g|h| - b_g
            const float g = __fdividef(1.0f, 1.0f + __expf(earg)); // sigmoid(b_g - d_g|h|)
            const float hn = fmaf(cf, g, alpha * h);
            const float sg = __fdividef(1.0f, 1.0f + __expf(-hn));
            outs[(size_t)t * S + j] = hn * hn * sg;
            if (writeH) hout[(size_t)(t + 1) * S + j] = hn;
            h = hn;
        }
        __syncthreads();
        // refill this slot (dummy t0=0 reload once past the end; never consumed)
        int tn = (k + SNB) * SCH;
        if (tn > T_DIM - SCH) tn = 0;
        SC_ISSUE(slot, tn);
    }
    CP_WAIT0();
#undef SC_ISSUE
}

// ========================= launch =========================
extern "C" void kernel_launch(void* const* d_in, const int* in_sizes, int n_in,
                              void* d_out, int out_size)
{
    const float* x  = (const float*)d_in[0];
    const float* Wa = (const float*)d_in[1];
    const float* ba = (const float*)d_in[2];
    const float* dg = (const float*)d_in[3];
    const float* bg = (const float*)d_in[4];
    const float* Wx = (const float*)d_in[5];
    const float* bv = (const float*)d_in[6];

    float* out  = (float*)d_out;
    float* outs = out;
    float* hout = out + (size_t)M_DIM * D_DIM;
    const int writeH = (out_size > M_DIM * D_DIM) ? 1 : 0;

    // Precompute: x and remapped weights -> fp16
    split_x_kernel<<<(int)(((size_t)M_DIM * D_DIM / 4) / 256), 256>>>(x);
    split_w_kernel<<<(2 * D_DIM * D_DIM / 4) / 256, 256>>>(Wa, Wx);

    static int smem_set = 0;
    if (!smem_set) {
        cudaFuncSetAttribute(gemm_mma, cudaFuncAttributeMaxDynamicSharedMemorySize, SMEM_DYN);
        smem_set = 1;
    }
    dim3 grid(D_DIM / 64, M_DIM / 128);   // (16, 256), N fastest for x L2 reuse
    gemm_mma<<<grid, 256, SMEM_DYN>>>(ba, bv);

    scan_kernel<<<256, 64>>>(dg, bg, outs, hout, writeH);
}

// round 7
// speedup vs baseline: 1.9781x; 1.0059x over previous
#include <cuda_runtime.h>
#include <cuda_fp16.h>
#include <stdint.h>
#include <stddef.h>

// Problem dims (fixed by the reference)
#define T_DIM 2048
#define B_DIM 16
#define D_DIM 1024
#define M_DIM (T_DIM * B_DIM)   // 32768

// Scratch (static __device__; no cudaMalloc allowed)
__device__ float2 g_ac[(size_t)M_DIM * D_DIM];         // {alpha, c}
__device__ __half gXh[(size_t)M_DIM * D_DIM];          // x (fp16 rn)
__device__ __half gW[(size_t)16 * 128 * D_DIM];        // remapped Wa|Wx, fp16

// ===================== common helpers =====================
static __device__ __forceinline__ uint32_t pack2(__half a, __half b) {
    return (uint32_t)__half_as_ushort(a) | ((uint32_t)__half_as_ushort(b) << 16);
}
static __device__ __forceinline__ uint32_t smem_u32(const void* p) {
    uint32_t a;
    asm("{ .reg .u64 t; cvta.to.shared.u64 t, %1; cvt.u32.u64 %0, t; }" : "=r"(a) : "l"(p));
    return a;
}
static __device__ __forceinline__ void cp16(uint32_t dst, const void* src) {
    asm volatile("cp.async.cg.shared.global [%0], [%1], 16;" :: "r"(dst), "l"(src) : "memory");
}
#define CP_COMMIT() asm volatile("cp.async.commit_group;" ::: "memory")
#define CP_WAIT0()  asm volatile("cp.async.wait_group 0;" ::: "memory")
#define CP_WAIT3()  asm volatile("cp.async.wait_group 3;" ::: "memory")
#define CP_WAIT5()  asm volatile("cp.async.wait_group 5;" ::: "memory")

// ===================== precompute kernels =====================
__global__ void __launch_bounds__(256)
split_x_kernel(const float* __restrict__ x) {
    const size_t idx = (size_t)blockIdx.x * 256 + threadIdx.x;  // float4 index
    float4 v = ((const float4*)x)[idx];
    ((uint2*)gXh)[idx] = make_uint2(
        pack2(__float2half_rn(v.x), __float2half_rn(v.y)),
        pack2(__float2half_rn(v.z), __float2half_rn(v.w)));
}

// Remap weights: dest row (n>>6)*128 + m*64 + (n&63), m=0 -> Wa, m=1 -> Wx
__global__ void __launch_bounds__(256)
split_w_kernel(const float* __restrict__ Wa, const float* __restrict__ Wx) {
    const int e = blockIdx.x * 256 + threadIdx.x;   // float4 index over 2*1024*1024/4
    const int m = e >> 18;                           // 0: Wa, 1: Wx
    const int rem = e & 262143;
    const int n = rem >> 8;                          // source row
    const int c4 = rem & 255;                        // float4 col
    const float* src = m ? Wx : Wa;
    float4 v = ((const float4*)(src + (size_t)n * D_DIM))[c4];
    const size_t drow = (size_t)(n >> 6) * 128 + m * 64 + (n & 63);
    ((uint2*)gW)[drow * 256 + c4] = make_uint2(
        pack2(__float2half_rn(v.x), __float2half_rn(v.y)),
        pack2(__float2half_rn(v.z), __float2half_rn(v.w)));
}

// ===================== GEMM (fp16 mma.sync, deep cp.async pipeline) =====================
// Per CTA: M=128 rows of x, N=64 output cols for BOTH matrices (B tile = Wa64|Wx64).
#define BK 64
#define ROWP 144                       // padded row pitch bytes (64 fp16 = 128B + 16B pad)
#define PART 18432                     // 128 rows * 144B
#define STAGE_BYTES (2 * PART)         // A | W = 36864
#define NSTAGE 5
#define SMEM_DYN (NSTAGE * STAGE_BYTES)   // 184320

#define LDSM4(R, A) \
    asm volatile("ldmatrix.sync.aligned.m8n8.x4.shared.b16 {%0,%1,%2,%3}, [%4];" \
        : "=r"((R)[0]), "=r"((R)[1]), "=r"((R)[2]), "=r"((R)[3]) : "r"(A))

static __device__ __forceinline__ void mma_fp16(float* c, const uint32_t* a, const uint32_t* b) {
    asm volatile(
        "mma.sync.aligned.m16n8k16.row.col.f32.f16.f16.f32 "
        "{%0,%1,%2,%3}, {%4,%5,%6,%7}, {%8,%9}, {%0,%1,%2,%3};\n"
        : "+f"(c[0]), "+f"(c[1]), "+f"(c[2]), "+f"(c[3])
        : "r"(a[0]), "r"(a[1]), "r"(a[2]), "r"(a[3]), "r"(b[0]), "r"(b[1]));
}

extern __shared__ char dsmem[];

__global__ void __launch_bounds__(256, 1)
gemm_mma(const float* __restrict__ ba, const float* __restrict__ bv)
{
    const int tid = threadIdx.x;
    const int warp = tid >> 5;
    const int lane = tid & 31;
    const int n_base = blockIdx.x * 64;
    const int m_base = blockIdx.y * 128;
    const int wrow_base = blockIdx.x * 128;   // remapped weight row base

    const uint32_t sb = smem_u32(dsmem);

    // --- cp.async tile loader: 2 arrays x 1024 16B-chunks, 4 chunks/thread/array ---
#define ISSUE_LOAD(KK, SBASE) do {                                                    \
    const uint32_t sA = (SBASE);                                                      \
    _Pragma("unroll")                                                                 \
    for (int q = 0; q < 4; q++) {                                                     \
        const int idx = tid + 256 * q;                                                \
        const int row = idx >> 3;                                                     \
        const int c16 = idx & 7;                                                      \
        const size_t xo = ((size_t)(m_base + row) * D_DIM + (KK) + c16 * 8) * 2;      \
        const size_t wo = ((size_t)(wrow_base + row) * D_DIM + (KK) + c16 * 8) * 2;   \
        const uint32_t so = (uint32_t)(row * ROWP + c16 * 16);                        \
        cp16(sA + so,        (const char*)gXh + xo);                                  \
        cp16(sA + PART + so, (const char*)gW  + wo);                                  \
    }                                                                                 \
    CP_COMMIT();                                                                      \
} while (0)

    // warp tiling: wm in {0,64}, wn in {0,16,32,48}
    const int wm = (warp >> 2) * 64;
    const int wn = (warp & 3) * 16;
    const int grp = lane >> 2;
    const int tig = lane & 3;

    float accA[4][2][4], accX[4][2][4];
#pragma unroll
    for (int i = 0; i < 4; i++)
#pragma unroll
        for (int j = 0; j < 2; j++)
#pragma unroll
            for (int r = 0; r < 4; r++) { accA[i][j][r] = 0.f; accX[i][j][r] = 0.f; }

    // ldmatrix per-lane address components
    const int rowA = ((lane >> 3) & 1) * 8 + (lane & 7);
    const int khalfA = lane >> 4;
    const int rowB = ((lane >> 4) << 3) + (lane & 7);
    const int khalfB = (lane >> 3) & 1;

    // Prologue: 4 groups in flight
    ISSUE_LOAD(0, sb);
    ISSUE_LOAD(BK, sb + STAGE_BYTES);
    ISSUE_LOAD(2 * BK, sb + 2 * STAGE_BYTES);
    ISSUE_LOAD(3 * BK, sb + 3 * STAGE_BYTES);

    for (int kc = 0; kc < 16; kc++) {
        CP_WAIT3();           // oldest group (kc) landed
        __syncthreads();      // all warps done consuming slot (kc-1)%5 and see landed data
        if (kc + 4 < 16)
            ISSUE_LOAD((kc + 4) * BK, sb + ((kc + 4) % NSTAGE) * STAGE_BYTES);

        const uint32_t stage = sb + (kc % NSTAGE) * STAGE_BYTES;
        const uint32_t aBase = stage + (uint32_t)((wm + rowA) * ROWP + khalfA * 16);
        const uint32_t bBase = stage + PART + (uint32_t)((wn + rowB) * ROWP + khalfB * 16);

#pragma unroll
        for (int ks = 0; ks < 4; ks++) {
            const uint32_t ka = aBase + ks * 32;
            const uint32_t kb = bBase + ks * 32;
            uint32_t ah[4][4];
#pragma unroll
            for (int i = 0; i < 4; i++)
                LDSM4(ah[i], ka + i * (16 * ROWP));
            uint32_t bA[4], bX[4];
            LDSM4(bA, kb);                         // Wa rows (0..63)
            LDSM4(bX, kb + 64 * ROWP);             // Wx rows (64..127)
#pragma unroll
            for (int i = 0; i < 4; i++)
#pragma unroll
                for (int j = 0; j < 2; j++) {
                    mma_fp16(accA[i][j], ah[i], &bA[j * 2]);
                    mma_fp16(accX[i][j], ah[i], &bX[j * 2]);
                }
        }
    }
#undef ISSUE_LOAD
    CP_WAIT0();

    // Epilogue: alpha = sigmoid(uA + ba); c = (1-alpha)*tanh(uX + bv)
#pragma unroll
    for (int i = 0; i < 4; i++)
#pragma unroll
        for (int j = 0; j < 2; j++) {
            const int mrow = m_base + wm + i * 16 + grp;
            const int ncol = n_base + wn + j * 8 + tig * 2;
            const float ba0 = ba[ncol], ba1 = ba[ncol + 1];
            const float bv0 = bv[ncol], bv1 = bv[ncol + 1];
#pragma unroll
            for (int half = 0; half < 2; half++) {
                const int m = mrow + half * 8;
                float uA0 = accA[i][j][half * 2 + 0] + ba0;
                float uA1 = accA[i][j][half * 2 + 1] + ba1;
                float uX0 = accX[i][j][half * 2 + 0] + bv0;
                float uX1 = accX[i][j][half * 2 + 1] + bv1;
                float al0 = 1.0f / (1.0f + __expf(-uA0));
                float al1 = 1.0f / (1.0f + __expf(-uA1));
                float c0v = (1.0f - al0) * tanhf(uX0);
                float c1v = (1.0f - al1) * tanhf(uX1);
                g_ac[(size_t)m * D_DIM + ncol]     = make_float2(al0, c0v);
                g_ac[(size_t)m * D_DIM + ncol + 1] = make_float2(al1, c1v);
            }
        }
}

// ===================== Sequential scan: cp.async deep pipeline (unchanged, passing) =====
#define SNB 6
#define SCH 16

__global__ void __launch_bounds__(64)
scan_kernel(const float* __restrict__ dgv, const float* __restrict__ bgv,
            float* __restrict__ outs, float* __restrict__ hout, int writeH)
{
    __shared__ float2 sbuf[SNB][SCH][64];
    const int S = B_DIM * D_DIM;   // 16384 columns
    const int tid = threadIdx.x;
    const int j0 = blockIdx.x * 64;
    const int j = j0 + tid;
    const int dcol = j & (D_DIM - 1);
    const float dg  = dgv[dcol];
    const float nbg = -bgv[dcol];

#define SC_ISSUE(slot, t0) do {                                                  \
    _Pragma("unroll")                                                            \
    for (int q = 0; q < 8; q++) {                                                \
        const int idx = tid + 64 * q;                                            \
        const int row = idx >> 5;        /* 0..15 */                             \
        const int ch  = idx & 31;        /* 0..31 (16B chunks) */                \
        cp16(smem_u32(&sbuf[slot][row][ch * 2]),                                 \
             (const char*)&g_ac[(size_t)((t0) + row) * S + j0 + ch * 2]);        \
    }                                                                            \
    CP_COMMIT();                                                                 \
} while (0)

    float h = 0.0f;
    if (writeH) hout[j] = 0.0f;

#pragma unroll
    for (int s = 0; s < SNB; s++)
        SC_ISSUE(s, s * SCH);

    for (int k = 0; k < T_DIM / SCH; k++) {
        CP_WAIT5();
        __syncthreads();
        const int slot = k % SNB;
#pragma unroll
        for (int i = 0; i < SCH; i++) {
            const float2 ac = sbuf[slot][i][tid];
            const int t = k * SCH + i;
            const float alpha = ac.x, cf = ac.y;
            const float earg = fmaf(dg, fabsf(h), nbg);            // d_g|h| - b_g
            const float g = __fdividef(1.0f, 1.0f + __expf(earg)); // sigmoid(b_g - d_g|h|)
            const float hn = fmaf(cf, g, alpha * h);
            const float sg = __fdividef(1.0f, 1.0f + __expf(-hn));
            outs[(size_t)t * S + j] = hn * hn * sg;
            if (writeH) hout[(size_t)(t + 1) * S + j] = hn;
            h = hn;
        }
        __syncthreads();
        // refill this slot (dummy t0=0 reload once past the end; never consumed)
        int tn = (k + SNB) * SCH;
        if (tn > T_DIM - SCH) tn = 0;
        SC_ISSUE(slot, tn);
    }
    CP_WAIT0();
#undef SC_ISSUE
}

// ========================= launch =========================
extern "C" void kernel_launch(void* const* d_in, const int* in_sizes, int n_in,
                              void* d_out, int out_size)
{
    const float* x  = (const float*)d_in[0];
    const float* Wa = (const float*)d_in[1];
    const float* ba = (const float*)d_in[2];
    const float* dg = (const float*)d_in[3];
    const float* bg = (const float*)d_in[4];
    const float* Wx = (const float*)d_in[5];
    const float* bv = (const float*)d_in[6];

    float* out  = (float*)d_out;
    float* outs = out;
    float* hout = out + (size_t)M_DIM * D_DIM;
    const int writeH = (out_size > M_DIM * D_DIM) ? 1 : 0;

    // Precompute: x and remapped weights -> fp16
    split_x_kernel<<<(int)(((size_t)M_DIM * D_DIM / 4) / 256), 256>>>(x);
    split_w_kernel<<<(2 * D_DIM * D_DIM / 4) / 256, 256>>>(Wa, Wx);

    static int smem_set = 0;
    if (!smem_set) {
        cudaFuncSetAttribute(gemm_mma, cudaFuncAttributeMaxDynamicSharedMemorySize, SMEM_DYN);
        smem_set = 1;
    }
    dim3 grid(D_DIM / 64, M_DIM / 128);   // (16, 256), N fastest for x L2 reuse
    gemm_mma<<<grid, 256, SMEM_DYN>>>(ba, bv);

    scan_kernel<<<256, 64>>>(dg, bg, outs, hout, writeH);
}

// round 8
// speedup vs baseline: 3.4644x; 1.7514x over previous
#include <cuda_runtime.h>
#include <cuda_fp16.h>
#include <stdint.h>
#include <stddef.h>

// Problem dims (fixed by the reference)
#define T_DIM 2048
#define B_DIM 16
#define D_DIM 1024
#define M_DIM (T_DIM * B_DIM)   // 32768

// Scratch (static __device__; no cudaMalloc allowed)
__device__ float2 g_ac[(size_t)M_DIM * D_DIM];         // {alpha, c}
__device__ __half gXh[(size_t)M_DIM * D_DIM];          // x (fp16 rn)
__device__ __half gW[(size_t)16 * 128 * D_DIM];        // remapped Wa|Wx, fp16

// ===================== common helpers =====================
static __device__ __forceinline__ uint32_t pack2(__half a, __half b) {
    return (uint32_t)__half_as_ushort(a) | ((uint32_t)__half_as_ushort(b) << 16);
}
static __device__ __forceinline__ uint32_t smem_u32(const void* p) {
    uint32_t a;
    asm("{ .reg .u64 t; cvta.to.shared.u64 t, %1; cvt.u32.u64 %0, t; }" : "=r"(a) : "l"(p));
    return a;
}
static __device__ __forceinline__ void cp16(uint32_t dst, const void* src) {
    asm volatile("cp.async.cg.shared.global [%0], [%1], 16;" :: "r"(dst), "l"(src) : "memory");
}
#define CP_COMMIT() asm volatile("cp.async.commit_group;" ::: "memory")
#define CP_WAIT0()  asm volatile("cp.async.wait_group 0;" ::: "memory")
#define CP_WAIT2()  asm volatile("cp.async.wait_group 2;" ::: "memory")
#define CP_WAIT5()  asm volatile("cp.async.wait_group 5;" ::: "memory")

// ===================== precompute kernels =====================
__global__ void __launch_bounds__(256)
split_x_kernel(const float* __restrict__ x) {
    const size_t idx = (size_t)blockIdx.x * 256 + threadIdx.x;  // float4 index
    float4 v = ((const float4*)x)[idx];
    ((uint2*)gXh)[idx] = make_uint2(
        pack2(__float2half_rn(v.x), __float2half_rn(v.y)),
        pack2(__float2half_rn(v.z), __float2half_rn(v.w)));
}

// Remap weights: dest row (n>>6)*128 + m*64 + (n&63), m=0 -> Wa, m=1 -> Wx
__global__ void __launch_bounds__(256)
split_w_kernel(const float* __restrict__ Wa, const float* __restrict__ Wx) {
    const int e = blockIdx.x * 256 + threadIdx.x;   // float4 index over 2*1024*1024/4
    const int m = e >> 18;                           // 0: Wa, 1: Wx
    const int rem = e & 262143;
    const int n = rem >> 8;                          // source row
    const int c4 = rem & 255;                        // float4 col
    const float* src = m ? Wx : Wa;
    float4 v = ((const float4*)(src + (size_t)n * D_DIM))[c4];
    const size_t drow = (size_t)(n >> 6) * 128 + m * 64 + (n & 63);
    ((uint2*)gW)[drow * 256 + c4] = make_uint2(
        pack2(__float2half_rn(v.x), __float2half_rn(v.y)),
        pack2(__float2half_rn(v.z), __float2half_rn(v.w)));
}

// ===================== GEMM (fp16 mma.sync, BM=256, 512 threads) =====================
// Per CTA: M=256 rows of x, N=64 output cols for BOTH matrices (W tile = Wa64|Wx64).
#define BK 64
#define ROWP 144                        // padded row pitch bytes (64 fp16 = 128B + 16B pad)
#define A_PART (256 * ROWP)             // 36864
#define W_PART (128 * ROWP)             // 18432
#define STAGE_BYTES (A_PART + W_PART)   // 55296
#define NSTAGE 4
#define SMEM_DYN (NSTAGE * STAGE_BYTES) // 221184

#define LDSM4(R, A) \
    asm volatile("ldmatrix.sync.aligned.m8n8.x4.shared.b16 {%0,%1,%2,%3}, [%4];" \
        : "=r"((R)[0]), "=r"((R)[1]), "=r"((R)[2]), "=r"((R)[3]) : "r"(A))

static __device__ __forceinline__ void mma_fp16(float* c, const uint32_t* a, const uint32_t* b) {
    asm volatile(
        "mma.sync.aligned.m16n8k16.row.col.f32.f16.f16.f32 "
        "{%0,%1,%2,%3}, {%4,%5,%6,%7}, {%8,%9}, {%0,%1,%2,%3};\n"
        : "+f"(c[0]), "+f"(c[1]), "+f"(c[2]), "+f"(c[3])
        : "r"(a[0]), "r"(a[1]), "r"(a[2]), "r"(a[3]), "r"(b[0]), "r"(b[1]));
}

extern __shared__ char dsmem[];

__global__ void __launch_bounds__(512, 1)
gemm_mma(const float* __restrict__ ba, const float* __restrict__ bv)
{
    const int tid = threadIdx.x;
    const int warp = tid >> 5;
    const int lane = tid & 31;
    const int n_base = blockIdx.x * 64;
    const int m_base = blockIdx.y * 256;
    const int wrow_base = blockIdx.x * 128;   // remapped weight row base

    const uint32_t sb = smem_u32(dsmem);

    // --- cp.async tile loader: A = 2048 16B-chunks (q=0..3), W = 1024 chunks (q=4..5) ---
#define ISSUE_LOAD(KK, SBASE) do {                                                    \
    const uint32_t sA = (SBASE);                                                      \
    _Pragma("unroll")                                                                 \
    for (int q = 0; q < 4; q++) {                                                     \
        const int idx = tid + 512 * q;                                                \
        const int row = idx >> 3;                                                     \
        const int c16 = idx & 7;                                                      \
        const size_t xo = ((size_t)(m_base + row) * D_DIM + (KK) + c16 * 8) * 2;      \
        cp16(sA + (uint32_t)(row * ROWP + c16 * 16), (const char*)gXh + xo);          \
    }                                                                                 \
    _Pragma("unroll")                                                                 \
    for (int q = 0; q < 2; q++) {                                                     \
        const int idx = tid + 512 * q;                                                \
        const int row = idx >> 3;                                                     \
        const int c16 = idx & 7;                                                      \
        const size_t wo = ((size_t)(wrow_base + row) * D_DIM + (KK) + c16 * 8) * 2;   \
        cp16(sA + A_PART + (uint32_t)(row * ROWP + c16 * 16), (const char*)gW + wo);  \
    }                                                                                 \
    CP_COMMIT();                                                                      \
} while (0)

    // warp tiling: 16 warps; wm in {0,64,128,192}, wn in {0,16,32,48}
    const int wm = (warp >> 2) * 64;
    const int wn = (warp & 3) * 16;
    const int grp = lane >> 2;
    const int tig = lane & 3;

    float accA[4][2][4], accX[4][2][4];
#pragma unroll
    for (int i = 0; i < 4; i++)
#pragma unroll
        for (int j = 0; j < 2; j++)
#pragma unroll
            for (int r = 0; r < 4; r++) { accA[i][j][r] = 0.f; accX[i][j][r] = 0.f; }

    // ldmatrix per-lane address components
    const int rowA = ((lane >> 3) & 1) * 8 + (lane & 7);
    const int khalfA = lane >> 4;
    const int rowB = ((lane >> 4) << 3) + (lane & 7);
    const int khalfB = (lane >> 3) & 1;

    // Prologue: 3 groups in flight
    ISSUE_LOAD(0, sb);
    ISSUE_LOAD(BK, sb + STAGE_BYTES);
    ISSUE_LOAD(2 * BK, sb + 2 * STAGE_BYTES);

    for (int kc = 0; kc < 16; kc++) {
        CP_WAIT2();           // oldest group (kc) landed
        __syncthreads();      // all warps done consuming slot (kc-1)%4 and see landed data
        if (kc + 3 < 16)
            ISSUE_LOAD((kc + 3) * BK, sb + ((kc + 3) % NSTAGE) * STAGE_BYTES);

        const uint32_t stage = sb + (kc % NSTAGE) * STAGE_BYTES;
        const uint32_t aBase = stage + (uint32_t)((wm + rowA) * ROWP + khalfA * 16);
        const uint32_t bBase = stage + A_PART + (uint32_t)((wn + rowB) * ROWP + khalfB * 16);

#pragma unroll
        for (int ks = 0; ks < 4; ks++) {
            const uint32_t ka = aBase + ks * 32;
            const uint32_t kb = bBase + ks * 32;
            uint32_t ah[4][4];
#pragma unroll
            for (int i = 0; i < 4; i++)
                LDSM4(ah[i], ka + i * (16 * ROWP));
            uint32_t bA[4], bX[4];
            LDSM4(bA, kb);                         // Wa rows (0..63)
            LDSM4(bX, kb + 64 * ROWP);             // Wx rows (64..127)
#pragma unroll
            for (int i = 0; i < 4; i++)
#pragma unroll
                for (int j = 0; j < 2; j++) {
                    mma_fp16(accA[i][j], ah[i], &bA[j * 2]);
                    mma_fp16(accX[i][j], ah[i], &bX[j * 2]);
                }
        }
    }
#undef ISSUE_LOAD
    CP_WAIT0();

    // Epilogue: alpha = sigmoid(uA + ba); c = (1-alpha)*tanh(uX + bv)
#pragma unroll
    for (int i = 0; i < 4; i++)
#pragma unroll
        for (int j = 0; j < 2; j++) {
            const int mrow = m_base + wm + i * 16 + grp;
            const int ncol = n_base + wn + j * 8 + tig * 2;
            const float ba0 = ba[ncol], ba1 = ba[ncol + 1];
            const float bv0 = bv[ncol], bv1 = bv[ncol + 1];
#pragma unroll
            for (int half = 0; half < 2; half++) {
                const int m = mrow + half * 8;
                float uA0 = accA[i][j][half * 2 + 0] + ba0;
                float uA1 = accA[i][j][half * 2 + 1] + ba1;
                float uX0 = accX[i][j][half * 2 + 0] + bv0;
                float uX1 = accX[i][j][half * 2 + 1] + bv1;
                float al0 = 1.0f / (1.0f + __expf(-uA0));
                float al1 = 1.0f / (1.0f + __expf(-uA1));
                float c0v = (1.0f - al0) * tanhf(uX0);
                float c1v = (1.0f - al1) * tanhf(uX1);
                g_ac[(size_t)m * D_DIM + ncol]     = make_float2(al0, c0v);
                g_ac[(size_t)m * D_DIM + ncol + 1] = make_float2(al1, c1v);
            }
        }
}

// ===================== Sequential scan: cp.async deep pipeline (unchanged, passing) =====
#define SNB 6
#define SCH 16

__global__ void __launch_bounds__(64)
scan_kernel(const float* __restrict__ dgv, const float* __restrict__ bgv,
            float* __restrict__ outs, float* __restrict__ hout, int writeH)
{
    __shared__ float2 sbuf[SNB][SCH][64];
    const int S = B_DIM * D_DIM;   // 16384 columns
    const int tid = threadIdx.x;
    const int j0 = blockIdx.x * 64;
    const int j = j0 + tid;
    const int dcol = j & (D_DIM - 1);
    const float dg  = dgv[dcol];
    const float nbg = -bgv[dcol];

#define SC_ISSUE(slot, t0) do {                                                  \
    _Pragma("unroll")                                                            \
    for (int q = 0; q < 8; q++) {                                                \
        const int idx = tid + 64 * q;                                            \
        const int row = idx >> 5;        /* 0..15 */                             \
        const int ch  = idx & 31;        /* 0..31 (16B chunks) */                \
        cp16(smem_u32(&sbuf[slot][row][ch * 2]),                                 \
             (const char*)&g_ac[(size_t)((t0) + row) * S + j0 + ch * 2]);        \
    }                                                                            \
    CP_COMMIT();                                                                 \
} while (0)

    float h = 0.0f;
    if (writeH) hout[j] = 0.0f;

#pragma unroll
    for (int s = 0; s < SNB; s++)
        SC_ISSUE(s, s * SCH);

    for (int k = 0; k < T_DIM / SCH; k++) {
        CP_WAIT5();
        __syncthreads();
        const int slot = k % SNB;
#pragma unroll
        for (int i = 0; i < SCH; i++) {
            const float2 ac = sbuf[slot][i][tid];
            const int t = k * SCH + i;
            const float alpha = ac.x, cf = ac.y;
            const float earg = fmaf(dg, fabsf(h), nbg);            // d_g|h| - b_g
            const float g = __fdividef(1.0f, 1.0f + __expf(earg)); // sigmoid(b_g - d_g|h|)
            const float hn = fmaf(cf, g, alpha * h);
            const float sg = __fdividef(1.0f, 1.0f + __expf(-hn));
            outs[(size_t)t * S + j] = hn * hn * sg;
            if (writeH) hout[(size_t)(t + 1) * S + j] = hn;
            h = hn;
        }
        __syncthreads();
        // refill this slot (dummy t0=0 reload once past the end; never consumed)
        int tn = (k + SNB) * SCH;
        if (tn > T_DIM - SCH) tn = 0;
        SC_ISSUE(slot, tn);
    }
    CP_WAIT0();
#undef SC_ISSUE
}

// ========================= launch =========================
extern "C" void kernel_launch(void* const* d_in, const int* in_sizes, int n_in,
                              void* d_out, int out_size)
{
    const float* x  = (const float*)d_in[0];
    const float* Wa = (const float*)d_in[1];
    const float* ba = (const float*)d_in[2];
    const float* dg = (const float*)d_in[3];
    const float* bg = (const float*)d_in[4];
    const float* Wx = (const float*)d_in[5];
    const float* bv = (const float*)d_in[6];

    float* out  = (float*)d_out;
    float* outs = out;
    float* hout = out + (size_t)M_DIM * D_DIM;
    const int writeH = (out_size > M_DIM * D_DIM) ? 1 : 0;

    // Precompute: x and remapped weights -> fp16
    split_x_kernel<<<(int)(((size_t)M_DIM * D_DIM / 4) / 256), 256>>>(x);
    split_w_kernel<<<(2 * D_DIM * D_DIM / 4) / 256, 256>>>(Wa, Wx);

    static int smem_set = 0;
    if (!smem_set) {
        cudaFuncSetAttribute(gemm_mma, cudaFuncAttributeMaxDynamicSharedMemorySize, SMEM_DYN);
        smem_set = 1;
    }
    dim3 grid(D_DIM / 64, M_DIM / 256);   // (16, 128), N fastest for x L2 reuse
    gemm_mma<<<grid, 512, SMEM_DYN>>>(ba, bv);

    scan_kernel<<<256, 64>>>(dg, bg, outs, hout, writeH);
}

// round 9
// speedup vs baseline: 3.4829x; 1.0054x over previous
#include <cuda_runtime.h>
#include <cuda_fp16.h>
#include <stdint.h>
#include <stddef.h>

// Problem dims (fixed by the reference)
#define T_DIM 2048
#define B_DIM 16
#define D_DIM 1024
#define M_DIM (T_DIM * B_DIM)   // 32768

// Scratch (static __device__; no cudaMalloc allowed)
__device__ float2 g_ac[(size_t)M_DIM * D_DIM];         // {alpha, c}
__device__ __half gXh[(size_t)M_DIM * D_DIM];          // x (fp16 rn)
__device__ __half gW[(size_t)16 * 128 * D_DIM];        // remapped Wa|Wx, fp16

// ===================== common helpers =====================
static __device__ __forceinline__ uint32_t pack2(__half a, __half b) {
    return (uint32_t)__half_as_ushort(a) | ((uint32_t)__half_as_ushort(b) << 16);
}
static __device__ __forceinline__ uint32_t smem_u32(const void* p) {
    uint32_t a;
    asm("{ .reg .u64 t; cvta.to.shared.u64 t, %1; cvt.u32.u64 %0, t; }" : "=r"(a) : "l"(p));
    return a;
}
static __device__ __forceinline__ void cp16(uint32_t dst, const void* src) {
    asm volatile("cp.async.cg.shared.global [%0], [%1], 16;" :: "r"(dst), "l"(src) : "memory");
}
#define CP_COMMIT() asm volatile("cp.async.commit_group;" ::: "memory")
#define CP_WAIT0()  asm volatile("cp.async.wait_group 0;" ::: "memory")
#define CP_WAIT2()  asm volatile("cp.async.wait_group 2;" ::: "memory")
#define CP_WAIT5()  asm volatile("cp.async.wait_group 5;" ::: "memory")

// ===================== precompute kernels =====================
__global__ void __launch_bounds__(256)
split_x_kernel(const float* __restrict__ x) {
    const size_t idx = (size_t)blockIdx.x * 256 + threadIdx.x;  // float4 index
    float4 v = ((const float4*)x)[idx];
    ((uint2*)gXh)[idx] = make_uint2(
        pack2(__float2half_rn(v.x), __float2half_rn(v.y)),
        pack2(__float2half_rn(v.z), __float2half_rn(v.w)));
}

// Remap weights: dest row (n>>6)*128 + m*64 + (n&63), m=0 -> Wa, m=1 -> Wx
__global__ void __launch_bounds__(256)
split_w_kernel(const float* __restrict__ Wa, const float* __restrict__ Wx) {
    const int e = blockIdx.x * 256 + threadIdx.x;   // float4 index over 2*1024*1024/4
    const int m = e >> 18;                           // 0: Wa, 1: Wx
    const int rem = e & 262143;
    const int n = rem >> 8;                          // source row
    const int c4 = rem & 255;                        // float4 col
    const float* src = m ? Wx : Wa;
    float4 v = ((const float4*)(src + (size_t)n * D_DIM))[c4];
    const size_t drow = (size_t)(n >> 6) * 128 + m * 64 + (n & 63);
    ((uint2*)gW)[drow * 256 + c4] = make_uint2(
        pack2(__float2half_rn(v.x), __float2half_rn(v.y)),
        pack2(__float2half_rn(v.z), __float2half_rn(v.w)));
}

// ===================== GEMM: BM=256, A via LDG+STS, W via cp.async =====================
#define BK 64
#define ROWP 144                        // padded row pitch bytes (64 fp16 = 128B + 16B pad)
#define A_PART (256 * ROWP)             // 36864
#define W_PART (128 * ROWP)             // 18432
#define A_STAGES 2
#define W_STAGES 4
#define SMEM_DYN (A_STAGES * A_PART + W_STAGES * W_PART)   // 147456

#define LDSM4(R, A) \
    asm volatile("ldmatrix.sync.aligned.m8n8.x4.shared.b16 {%0,%1,%2,%3}, [%4];" \
        : "=r"((R)[0]), "=r"((R)[1]), "=r"((R)[2]), "=r"((R)[3]) : "r"(A))

static __device__ __forceinline__ void mma_fp16(float* c, const uint32_t* a, const uint32_t* b) {
    asm volatile(
        "mma.sync.aligned.m16n8k16.row.col.f32.f16.f16.f32 "
        "{%0,%1,%2,%3}, {%4,%5,%6,%7}, {%8,%9}, {%0,%1,%2,%3};\n"
        : "+f"(c[0]), "+f"(c[1]), "+f"(c[2]), "+f"(c[3])
        : "r"(a[0]), "r"(a[1]), "r"(a[2]), "r"(a[3]), "r"(b[0]), "r"(b[1]));
}

extern __shared__ char dsmem[];

__global__ void __launch_bounds__(512, 1)
gemm_mma(const float* __restrict__ ba, const float* __restrict__ bv)
{
    const int tid = threadIdx.x;
    const int warp = tid >> 5;
    const int lane = tid & 31;
    const int n_base = blockIdx.x * 64;
    const int m_base = blockIdx.y * 256;
    const int wrow_base = blockIdx.x * 128;   // remapped weight row base

    const uint32_t sb = smem_u32(dsmem);               // A stages base
    const uint32_t wb = sb + A_STAGES * A_PART;        // W stages base

    // Per-thread A staging map: idx = tid + 512*q -> row 0..255, col-block 0..7
    const int arow = tid >> 3;         // row for q stride of 64 rows
    const int ac16 = tid & 7;

    // A data for one chunk: 4 x uint4 per thread (32 KB of payload)
    uint4 rA[4];
#define LDG_A(KK) do {                                                                \
    _Pragma("unroll")                                                                 \
    for (int q = 0; q < 4; q++) {                                                     \
        const int row = arow + 64 * q;                                                \
        rA[q] = *(const uint4*)&gXh[(size_t)(m_base + row) * D_DIM + (KK) + ac16 * 8];\
    } } while (0)

#define STS_A(SBASE) do {                                                             \
    _Pragma("unroll")                                                                 \
    for (int q = 0; q < 4; q++) {                                                     \
        const int row = arow + 64 * q;                                                \
        *(uint4*)(dsmem + ((SBASE) - sb) + row * ROWP + ac16 * 16) = rA[q];           \
    } } while (0)

#define ISSUE_W(KK, WSLOT) do {                                                       \
    const uint32_t wdst = wb + (WSLOT) * W_PART;                                      \
    _Pragma("unroll")                                                                 \
    for (int q = 0; q < 2; q++) {                                                     \
        const int idx = tid + 512 * q;                                                \
        const int row = idx >> 3;                                                     \
        const int c16 = idx & 7;                                                      \
        const size_t wo = ((size_t)(wrow_base + row) * D_DIM + (KK) + c16 * 8) * 2;   \
        cp16(wdst + (uint32_t)(row * ROWP + c16 * 16), (const char*)gW + wo);         \
    }                                                                                 \
    CP_COMMIT();                                                                      \
} while (0)

    // warp tiling: 16 warps; wm in {0,64,128,192}, wn in {0,16,32,48}
    const int wm = (warp >> 2) * 64;
    const int wn = (warp & 3) * 16;
    const int grp = lane >> 2;
    const int tig = lane & 3;

    float accA[4][2][4], accX[4][2][4];
#pragma unroll
    for (int i = 0; i < 4; i++)
#pragma unroll
        for (int j = 0; j < 2; j++)
#pragma unroll
            for (int r = 0; r < 4; r++) { accA[i][j][r] = 0.f; accX[i][j][r] = 0.f; }

    // ldmatrix per-lane address components
    const int rowA = ((lane >> 3) & 1) * 8 + (lane & 7);
    const int khalfA = lane >> 4;
    const int rowB = ((lane >> 4) << 3) + (lane & 7);
    const int khalfB = (lane >> 3) & 1;

    // Prologue: A chunk0 -> regs -> smem stage0; A chunk1 -> regs; W chunks 0..2 in flight
    LDG_A(0);
    ISSUE_W(0, 0);
    ISSUE_W(BK, 1);
    ISSUE_W(2 * BK, 2);
    STS_A(sb);
    LDG_A(BK);

    for (int kc = 0; kc < 16; kc++) {
        CP_WAIT2();           // W group kc landed (kc+1, kc+2 may be pending)
        __syncthreads();      // A STS of chunk kc visible; all warps done with stage (kc-1)
        if (kc + 1 < 16)
            STS_A(sb + ((kc + 1) & 1) * A_PART);     // chunk kc+1 from regs
        if (kc + 2 < 16)
            LDG_A((kc + 2) * BK);                     // chunk kc+2 into regs
        if (kc + 3 < 16) {
            ISSUE_W((kc + 3) * BK, (kc + 3) & 3);     // includes commit
        } else {
            CP_COMMIT();                              // keep one group per iteration
        }

        const uint32_t aStage = sb + (kc & 1) * A_PART;
        const uint32_t wStage = wb + (kc & 3) * W_PART;
        const uint32_t aBase = aStage + (uint32_t)((wm + rowA) * ROWP + khalfA * 16);
        const uint32_t bBase = wStage + (uint32_t)((wn + rowB) * ROWP + khalfB * 16);

#pragma unroll
        for (int ks = 0; ks < 4; ks++) {
            const uint32_t ka = aBase + ks * 32;
            const uint32_t kb = bBase + ks * 32;
            uint32_t ah[4][4];
#pragma unroll
            for (int i = 0; i < 4; i++)
                LDSM4(ah[i], ka + i * (16 * ROWP));
            uint32_t bA[4], bX[4];
            LDSM4(bA, kb);                         // Wa rows (0..63)
            LDSM4(bX, kb + 64 * ROWP);             // Wx rows (64..127)
#pragma unroll
            for (int i = 0; i < 4; i++)
#pragma unroll
                for (int j = 0; j < 2; j++) {
                    mma_fp16(accA[i][j], ah[i], &bA[j * 2]);
                    mma_fp16(accX[i][j], ah[i], &bX[j * 2]);
                }
        }
    }
    CP_WAIT0();
#undef LDG_A
#undef STS_A
#undef ISSUE_W

    // Epilogue: alpha = sigmoid(uA + ba); c = (1-alpha)*tanh(uX + bv)
#pragma unroll
    for (int i = 0; i < 4; i++)
#pragma unroll
        for (int j = 0; j < 2; j++) {
            const int mrow = m_base + wm + i * 16 + grp;
            const int ncol = n_base + wn + j * 8 + tig * 2;
            const float ba0 = ba[ncol], ba1 = ba[ncol + 1];
            const float bv0 = bv[ncol], bv1 = bv[ncol + 1];
#pragma unroll
            for (int half = 0; half < 2; half++) {
                const int m = mrow + half * 8;
                float uA0 = accA[i][j][half * 2 + 0] + ba0;
                float uA1 = accA[i][j][half * 2 + 1] + ba1;
                float uX0 = accX[i][j][half * 2 + 0] + bv0;
                float uX1 = accX[i][j][half * 2 + 1] + bv1;
                float al0 = 1.0f / (1.0f + __expf(-uA0));
                float al1 = 1.0f / (1.0f + __expf(-uA1));
                float c0v = (1.0f - al0) * tanhf(uX0);
                float c1v = (1.0f - al1) * tanhf(uX1);
                g_ac[(size_t)m * D_DIM + ncol]     = make_float2(al0, c0v);
                g_ac[(size_t)m * D_DIM + ncol + 1] = make_float2(al1, c1v);
            }
        }
}

// ===================== Sequential scan: cp.async deep pipeline (unchanged, passing) =====
#define SNB 6
#define SCH 16

__global__ void __launch_bounds__(64)
scan_kernel(const float* __restrict__ dgv, const float* __restrict__ bgv,
            float* __restrict__ outs, float* __restrict__ hout, int writeH)
{
    __shared__ float2 sbuf[SNB][SCH][64];
    const int S = B_DIM * D_DIM;   // 16384 columns
    const int tid = threadIdx.x;
    const int j0 = blockIdx.x * 64;
    const int j = j0 + tid;
    const int dcol = j & (D_DIM - 1);
    const float dg  = dgv[dcol];
    const float nbg = -bgv[dcol];

#define SC_ISSUE(slot, t0) do {                                                  \
    _Pragma("unroll")                                                            \
    for (int q = 0; q < 8; q++) {                                                \
        const int idx = tid + 64 * q;                                            \
        const int row = idx >> 5;        /* 0..15 */                             \
        const int ch  = idx & 31;        /* 0..31 (16B chunks) */                \
        cp16(smem_u32(&sbuf[slot][row][ch * 2]),                                 \
             (const char*)&g_ac[(size_t)((t0) + row) * S + j0 + ch * 2]);        \
    }                                                                            \
    CP_COMMIT();                                                                 \
} while (0)

    float h = 0.0f;
    if (writeH) hout[j] = 0.0f;

#pragma unroll
    for (int s = 0; s < SNB; s++)
        SC_ISSUE(s, s * SCH);

    for (int k = 0; k < T_DIM / SCH; k++) {
        CP_WAIT5();
        __syncthreads();
        const int slot = k % SNB;
#pragma unroll
        for (int i = 0; i < SCH; i++) {
            const float2 ac = sbuf[slot][i][tid];
            const int t = k * SCH + i;
            const float alpha = ac.x, cf = ac.y;
            const float earg = fmaf(dg, fabsf(h), nbg);            // d_g|h| - b_g
            const float g = __fdividef(1.0f, 1.0f + __expf(earg)); // sigmoid(b_g - d_g|h|)
            const float hn = fmaf(cf, g, alpha * h);
            const float sg = __fdividef(1.0f, 1.0f + __expf(-hn));
            outs[(size_t)t * S + j] = hn * hn * sg;
            if (writeH) hout[(size_t)(t + 1) * S + j] = hn;
            h = hn;
        }
        __syncthreads();
        // refill this slot (dummy t0=0 reload once past the end; never consumed)
        int tn = (k + SNB) * SCH;
        if (tn > T_DIM - SCH) tn = 0;
        SC_ISSUE(slot, tn);
    }
    CP_WAIT0();
#undef SC_ISSUE
}

// ========================= launch =========================
extern "C" void kernel_launch(void* const* d_in, const int* in_sizes, int n_in,
                              void* d_out, int out_size)
{
    const float* x  = (const float*)d_in[0];
    const float* Wa = (const float*)d_in[1];
    const float* ba = (const float*)d_in[2];
    const float* dg = (const float*)d_in[3];
    const float* bg = (const float*)d_in[4];
    const float* Wx = (const float*)d_in[5];
    const float* bv = (const float*)d_in[6];

    float* out  = (float*)d_out;
    float* outs = out;
    float* hout = out + (size_t)M_DIM * D_DIM;
    const int writeH = (out_size > M_DIM * D_DIM) ? 1 : 0;

    // Precompute: x and remapped weights -> fp16
    split_x_kernel<<<(int)(((size_t)M_DIM * D_DIM / 4) / 256), 256>>>(x);
    split_w_kernel<<<(2 * D_DIM * D_DIM / 4) / 256, 256>>>(Wa, Wx);

    static int smem_set = 0;
    if (!smem_set) {
        cudaFuncSetAttribute(gemm_mma, cudaFuncAttributeMaxDynamicSharedMemorySize, SMEM_DYN);
        smem_set = 1;
    }
    dim3 grid(D_DIM / 64, M_DIM / 256);   // (16, 128), N fastest for x L2 reuse
    gemm_mma<<<grid, 512, SMEM_DYN>>>(ba, bv);

    scan_kernel<<<256, 64>>>(dg, bg, outs, hout, writeH);
}